// round 14
// baseline (speedup 1.0000x reference)
#include <cuda_runtime.h>
#include <cuda_bf16.h>
#include <cstdint>
#include <cstddef>

// ---------------- problem constants ----------------
#define BATCH   64
#define SEQL    720      // L = 16 * 45
#define ENC     512      // C
#define NROWS   (BATCH*ENC)       // 32768
#define NFREQ   361               // rfft bins
#define H_FREQ  64
#define H1      128
#define H2      256
#define PREDL   720
#define PREDPAD 768      // padded M for the output GEMM

#define L1F     16       // first CT factor
#define L2F     45       // second CT factor
#define NB      48       // stage-1 output width: [cos 0..22 | pad | -sin 0..22 | pad]

// ---------------- scratch (device globals; no allocs allowed) ----------------
__device__ float g_basis45[L2F*NB];           // DFT45 half-spectrum basis
__device__ float g_cosl[SEQL];
__device__ float g_sinl[SEQL];
__device__ float g_xt  [(size_t)NROWS*SEQL];  // x channel-major (b,c,l)
__device__ float g_spec2[(size_t)NROWS*L1F*NB]; // stage-1 partial half-spectra
__device__ float4 g_coef4[(size_t)NROWS*32];  // (re*w, im*w, twid.x, twid.y)
__device__ int    g_coefI[(size_t)NROWS*32];  // selected freq
__device__ float g_filt[(size_t)NROWS*SEQL];
__device__ float g_h   [(size_t)NROWS*H_FREQ];
__device__ float g_z1  [(size_t)NROWS*H1];
__device__ float g_z   [(size_t)NROWS*H2];
__device__ float g_t   [(size_t)NROWS*H2];
__device__ float g_tT  [(size_t)NROWS*H2];    // t transposed per batch (b,h,c)
__device__ float g_cm  [(size_t)NROWS*H2];    // channel-mixed (b,h,c)
__device__ float g_wprojT[(size_t)PREDPAD*H2]; // w_proj^T padded; pad rows stay 0

// ---------------- LUT / basis fill ----------------
__global__ void fill_luts(float* __restrict__ basis45, float* __restrict__ cosl,
                          float* __restrict__ sinl) {
    int idx = blockIdx.x * blockDim.x + threadIdx.x;
    if (idx < SEQL) {
        double s, c;
        sincospi((double)(2 * idx) / (double)SEQL, &s, &c);
        cosl[idx] = (float)c;
        sinl[idx] = (float)s;
    }
    if (idx < L2F * NB) {
        int l2 = idx / NB, c = idx % NB;
        float v = 0.f;
        if (c < 23 || (c >= 24 && c < 47)) {
            int g = (c < 23) ? c : (c - 24);
            int a = (g * l2) % L2F;
            double s, cc;
            sincospi((double)(2 * a) / (double)L2F, &s, &cc);
            v = (c < 23) ? (float)cc : (float)(-s);
        }
        basis45[idx] = v;
    }
}

// ---------------- batched transpose (B,R,C) -> (B,C,R) ----------------
__global__ void transpose_batched(const float* __restrict__ in, float* __restrict__ out,
                                  int R, int C) {
    __shared__ float tile[32][33];
    int b = blockIdx.z;
    int c0 = blockIdx.x * 32, r0 = blockIdx.y * 32;
    const float* pin = in + (size_t)b * R * C;
    float* pout = out + (size_t)b * R * C;
    int tx = threadIdx.x, ty = threadIdx.y;
#pragma unroll
    for (int j = 0; j < 32; j += 8) {
        int r = r0 + ty + j, c = c0 + tx;
        if (r < R && c < C) tile[ty + j][tx] = pin[(size_t)r * C + c];
    }
    __syncthreads();
#pragma unroll
    for (int j = 0; j < 32; j += 8) {
        int c = c0 + ty + j, r = r0 + tx;
        if (c < C && r < R) pout[(size_t)c * R + r] = tile[tx][ty + j];
    }
}

// variant writing into an output with row stride ldo (for padded w_projT)
__global__ void transpose_ld(const float* __restrict__ in, float* __restrict__ out,
                             int R, int C, int ldo) {
    __shared__ float tile[32][33];
    int c0 = blockIdx.x * 32, r0 = blockIdx.y * 32;
    int tx = threadIdx.x, ty = threadIdx.y;
#pragma unroll
    for (int j = 0; j < 32; j += 8) {
        int r = r0 + ty + j, c = c0 + tx;
        if (r < R && c < C) tile[ty + j][tx] = in[(size_t)r * C + c];
    }
    __syncthreads();
#pragma unroll
    for (int j = 0; j < 32; j += 8) {
        int c = c0 + ty + j, r = r0 + tx;
        if (c < C && r < R) out[(size_t)c * ldo + r] = tile[tx][ty + j];
    }
}

// src: (B,C,L) channel-major; out: (B,L,C); out = xin - src^T
__global__ void transpose_sub(const float* __restrict__ src, const float* __restrict__ xin,
                              float* __restrict__ out, int L, int C) {
    __shared__ float tile[32][33];
    int b = blockIdx.z;
    int l0 = blockIdx.x * 32, c0 = blockIdx.y * 32;
    const float* ps = src + (size_t)b * C * L;
#pragma unroll
    for (int j = 0; j < 32; j += 8) {
        int c = c0 + threadIdx.y + j, l = l0 + threadIdx.x;
        if (c < C && l < L) tile[threadIdx.y + j][threadIdx.x] = ps[(size_t)c * L + l];
    }
    __syncthreads();
    size_t ob = (size_t)b * L * C;
#pragma unroll
    for (int j = 0; j < 32; j += 8) {
        int l = l0 + threadIdx.y + j, c = c0 + threadIdx.x;
        if (l < L && c < C) {
            float v = tile[threadIdx.x][threadIdx.y + j];
            if (xin) v = xin[ob + (size_t)l * C + c] - v;
            out[ob + (size_t)l * C + c] = v;
        }
    }
}

// ------- stage-1: per-block 8 xt rows x full DFT45 half-spectrum (fp32) -------
__global__ void __launch_bounds__(256) gemm_s1(
    const float* __restrict__ xt, const float* __restrict__ basis,
    float* __restrict__ spec2) {
    __shared__ float Axt[8][SEQL];
    __shared__ float Bs[L2F][NB];
    const int tid = threadIdx.x;
    const size_t base = (size_t)blockIdx.x * (8 * SEQL);

    {
        const float4* src = reinterpret_cast<const float4*>(xt + base);
        float4* dst = reinterpret_cast<float4*>(&Axt[0][0]);
        for (int i = tid; i < 8 * SEQL / 4; i += 256) dst[i] = src[i];
    }
    {
        const float4* src = reinterpret_cast<const float4*>(basis);
        float4* dst = reinterpret_cast<float4*>(&Bs[0][0]);
        for (int i = tid; i < L2F * NB / 4; i += 256) dst[i] = src[i];
    }
    __syncthreads();

    const int tm = (tid >> 3) * 4;
    const int tn = (tid & 7) * 6;
    const int orig = tm >> 4;
    const int l1b = tm & 15;

    float acc[4][6] = {};
#pragma unroll 15
    for (int k = 0; k < L2F; k++) {
        float4 av = *reinterpret_cast<const float4*>(&Axt[orig][l1b + 16 * k]);
        float2 b0 = *reinterpret_cast<const float2*>(&Bs[k][tn]);
        float2 b1 = *reinterpret_cast<const float2*>(&Bs[k][tn + 2]);
        float2 b2 = *reinterpret_cast<const float2*>(&Bs[k][tn + 4]);
        float a[4] = {av.x, av.y, av.z, av.w};
        float b[6] = {b0.x, b0.y, b1.x, b1.y, b2.x, b2.y};
#pragma unroll
        for (int i = 0; i < 4; i++)
#pragma unroll
            for (int j = 0; j < 6; j++)
                acc[i][j] = fmaf(a[i], b[j], acc[i][j]);
    }

    size_t gmbase = (size_t)blockIdx.x * 128 + tm;
#pragma unroll
    for (int i = 0; i < 4; i++) {
        float* orow = spec2 + (gmbase + i) * NB + tn;
#pragma unroll
        for (int j = 0; j < 6; j += 2)
            *reinterpret_cast<float2*>(&orow[j]) = make_float2(acc[i][j], acc[i][j + 1]);
    }
}

// ------- stage-2 twiddle combine + per-row top-k selection -> coef packs -------
__global__ void __launch_bounds__(128) combine_topk(
    const float* __restrict__ spec2, const int* __restrict__ kptr,
    const float* __restrict__ cosl, const float* __restrict__ sinl,
    float4* __restrict__ coef4, int* __restrict__ coefI) {
    int row = blockIdx.x;
    const float* srow = spec2 + (size_t)row * (L1F * NB);

    __shared__ float2 slut[SEQL];
    __shared__ float2 sS2[L1F][23];
    __shared__ float sXre[NFREQ], sXim[NFREQ], sMag[NFREQ];

    int tid = threadIdx.x;
    for (int i = tid; i < SEQL; i += 128) slut[i] = make_float2(cosl[i], sinl[i]);
    for (int i = tid; i < L1F * 23; i += 128) {
        int l1 = i / 23, g = i % 23;
        sS2[l1][g] = make_float2(srow[l1 * NB + g], srow[l1 * NB + 24 + g]);
    }
    __syncthreads();

    for (int f = tid; f < NFREQ; f += 128) {
        int g = f % L2F;
        int gc = g; float sgn = 1.f;
        if (g >= 23) { gc = L2F - g; sgn = -1.f; }
        float xr = 0.f, xi = 0.f;
        int a = 0;
#pragma unroll
        for (int l1 = 0; l1 < L1F; l1++) {
            float2 w = slut[a];
            float2 s = sS2[l1][gc];
            float sr = s.x;
            float si = sgn * s.y;
            xr = fmaf(sr, w.x, fmaf(si, w.y, xr));
            xi = fmaf(si, w.x, fmaf(-sr, w.y, xi));
            a += f; if (a >= SEQL) a -= SEQL;
        }
        sXre[f] = xr; sXim[f] = xi;
        sMag[f] = xr * xr + xi * xi;
    }
    __syncthreads();

    if (tid < 32) {
        int lane = tid;
        float mag[12];
#pragma unroll
        for (int j = 0; j < 12; j++) {
            int idx = lane + 32 * j;
            mag[j] = (idx < NFREQ) ? sMag[idx] : -1.f;
        }
        int k = *kptr;
        if (k > 32) k = 32;
        if (k < 0) k = 0;
        const float scale = 1.f / (float)SEQL;
        for (int it = 0; it < k; it++) {
            float best = -1.f; int bslot = 0;
#pragma unroll
            for (int j = 0; j < 12; j++)
                if (mag[j] > best) { best = mag[j]; bslot = j; }
            int bidx = lane + 32 * bslot;
#pragma unroll
            for (int o = 16; o > 0; o >>= 1) {
                float ov = __shfl_xor_sync(0xffffffffu, best, o);
                int   oi = __shfl_xor_sync(0xffffffffu, bidx, o);
                if (ov > best || (ov == best && oi < bidx)) { best = ov; bidx = oi; }
            }
            if ((bidx & 31) == lane) {
                int j = bidx >> 5;
                float w = (bidx == 0 || bidx == NFREQ - 1) ? scale : 2.f * scale;
                float2 tw = slut[bidx];
                coef4[(size_t)row * 32 + it] =
                    make_float4(sXre[bidx] * w, sXim[bidx] * w, tw.x, tw.y);
                coefI[(size_t)row * 32 + it] = bidx;
                mag[j] = -2.f;
            }
        }
    }
}

// ------- sparse rotation irfft from coef packs -------
__global__ void __launch_bounds__(256) reconstruct(
    const float4* __restrict__ coef4, const int* __restrict__ coefI,
    const int* __restrict__ kptr,
    const float* __restrict__ cosl, const float* __restrict__ sinl,
    float* __restrict__ filt) {
    int row = blockIdx.x;
    __shared__ float2 slut[SEQL];
    __shared__ float4 sc[32];
    __shared__ int    sf[32];

    int tid = threadIdx.x;
    for (int i = tid; i < SEQL; i += 256) slut[i] = make_float2(cosl[i], sinl[i]);
    int k = *kptr;
    if (k > 32) k = 32;
    if (k < 0) k = 0;
    if (tid < k) {
        sc[tid] = coef4[(size_t)row * 32 + tid];
        sf[tid] = coefI[(size_t)row * 32 + tid];
    }
    __syncthreads();

    float* outp = filt + (size_t)row * SEQL;
    if (tid < 240) {
        int t0 = 3 * tid;
        float acc0 = 0.f, acc1 = 0.f, acc2 = 0.f;
        for (int j = 0; j < k; j++) {
            float4 c4 = sc[j];
            int f = sf[j];
            float r = c4.x, m = c4.y;
            int a0 = (f * t0) % SEQL;
            float2 p0 = slut[a0];
            acc0 = fmaf(r, p0.x, fmaf(-m, p0.y, acc0));
            float2 p1;
            p1.x = fmaf(-p0.y, c4.w, p0.x * c4.z);
            p1.y = fmaf(p0.x, c4.w, p0.y * c4.z);
            acc1 = fmaf(r, p1.x, fmaf(-m, p1.y, acc1));
            float2 p2;
            p2.x = fmaf(-p1.y, c4.w, p1.x * c4.z);
            p2.y = fmaf(p1.x, c4.w, p1.y * c4.z);
            acc2 = fmaf(r, p2.x, fmaf(-m, p2.y, acc2));
        }
        outp[t0 + 0] = acc0;
        outp[t0 + 1] = acc1;
        outp[t0 + 2] = acc2;
    }
}

// ---------------- bf16 helpers ----------------
__device__ __forceinline__ void split_pack_bf16(float e, float o, uint32_t& hi, uint32_t& lo) {
    __nv_bfloat16 he = __float2bfloat16_rn(e);
    __nv_bfloat16 ho = __float2bfloat16_rn(o);
    float re = e - __bfloat162float(he);
    float ro = o - __bfloat162float(ho);
    __nv_bfloat16 le = __float2bfloat16_rn(re);
    __nv_bfloat16 lo2 = __float2bfloat16_rn(ro);
    unsigned short ue = *reinterpret_cast<unsigned short*>(&he);
    unsigned short uo = *reinterpret_cast<unsigned short*>(&ho);
    unsigned short ve = *reinterpret_cast<unsigned short*>(&le);
    unsigned short vo = *reinterpret_cast<unsigned short*>(&lo2);
    hi = ((uint32_t)uo << 16) | ue;
    lo = ((uint32_t)vo << 16) | ve;
}

__device__ __forceinline__ void mma_bf16(float* d, const uint32_t* a, const uint32_t* b) {
    asm volatile(
        "mma.sync.aligned.m16n8k16.row.col.f32.bf16.bf16.f32 "
        "{%0,%1,%2,%3}, {%4,%5,%6,%7}, {%8,%9}, {%0,%1,%2,%3};\n"
        : "+f"(d[0]), "+f"(d[1]), "+f"(d[2]), "+f"(d[3])
        : "r"(a[0]), "r"(a[1]), "r"(a[2]), "r"(a[3]), "r"(b[0]), "r"(b[1]));
}

// ------- tensor-core GEMM: 128M x 64N block, bf16 3-term split, m16n8k16 -------
// Double-buffered smem (one sync per k16 stage). z-batched via strides.
// MODE 0: +bias[col] ; 1: relu ; 2: relu(+Cin) ; 3: Cin + relu ; 5: +bias[row]
// M guarded in epilogue (A rows up to padded extent must be readable).
template <int MODE>
__global__ void __launch_bounds__(256) gemm_bf(
    const float* __restrict__ A, int lda,
    const float* __restrict__ B, int ldb,
    const float* __restrict__ bias,
    const float* __restrict__ Cin, int ldcin,
    float* __restrict__ C, int ldc,
    int M, int N, int K,
    long zA, long zB, long zCin, long zC) {
    __shared__ uint2 As[2][8][140];   // [buf][kp][m] (hi, lo)
    __shared__ uint2 Bs[2][8][76];    // [buf][kp][n]

    const size_t zi = blockIdx.z;
    A += zi * zA; B += zi * zB;
    if (Cin) Cin += zi * zCin;
    C += zi * zC;

    const int tid = threadIdx.x;
    const int m0 = blockIdx.y * 128, n0 = blockIdx.x * 64;
    const int lane = tid & 31, warp = tid >> 5;
    const int wm = warp & 3, wn = warp >> 2;
    const int m0w = wm * 32, n0w = wn * 32;
    const int kq = lane & 3, gq = lane >> 2;

    const int arow = tid >> 1, ak = (tid & 1) * 8, akp = (tid & 1) * 4;
    const int bkp = tid >> 5, bn2 = (tid & 31) * 2;

    float acc[2][4][4];
#pragma unroll
    for (int i = 0; i < 2; i++)
#pragma unroll
        for (int j = 0; j < 4; j++)
#pragma unroll
            for (int q = 0; q < 4; q++) acc[i][j][q] = 0.f;

    float4 aP0, aP1;
    float be[2], bo[2];

    auto prefetch = [&](int kb) {
        aP0 = *reinterpret_cast<const float4*>(&A[(size_t)(m0 + arow) * lda + kb + ak]);
        aP1 = *reinterpret_cast<const float4*>(&A[(size_t)(m0 + arow) * lda + kb + ak + 4]);
        const float* B0 = &B[(size_t)(kb + 2 * bkp) * ldb];
        const float* B1 = &B[(size_t)(kb + 2 * bkp + 1) * ldb];
#pragma unroll
        for (int i = 0; i < 2; i++) {
            int n = n0 + bn2 + i;
            be[i] = (n < N) ? B0[n] : 0.f;
            bo[i] = (n < N) ? B1[n] : 0.f;
        }
    };
    auto store_tile = [&](int buf) {
        float av[8] = {aP0.x, aP0.y, aP0.z, aP0.w, aP1.x, aP1.y, aP1.z, aP1.w};
#pragma unroll
        for (int i = 0; i < 4; i++) {
            uint32_t h, l;
            split_pack_bf16(av[2 * i], av[2 * i + 1], h, l);
            As[buf][akp + i][arow] = make_uint2(h, l);
        }
#pragma unroll
        for (int i = 0; i < 2; i++) {
            uint32_t h, l;
            split_pack_bf16(be[i], bo[i], h, l);
            Bs[buf][bkp][bn2 + i] = make_uint2(h, l);
        }
    };

    prefetch(0);
    store_tile(0);
    __syncthreads();

    const int nst = K / 16;
    for (int s = 0; s < nst; s++) {
        const int cur = s & 1;
        const bool more = (s + 1 < nst);
        if (more) prefetch(16 * (s + 1));

        uint32_t ah[2][4], al[2][4], bh[4][2], bl[4][2];
#pragma unroll
        for (int mi = 0; mi < 2; mi++) {
            int m = m0w + mi * 16 + gq;
            uint2 a00 = As[cur][kq][m],     a01 = As[cur][kq][m + 8];
            uint2 a10 = As[cur][kq + 4][m], a11 = As[cur][kq + 4][m + 8];
            ah[mi][0] = a00.x; ah[mi][1] = a01.x; ah[mi][2] = a10.x; ah[mi][3] = a11.x;
            al[mi][0] = a00.y; al[mi][1] = a01.y; al[mi][2] = a10.y; al[mi][3] = a11.y;
        }
#pragma unroll
        for (int ni = 0; ni < 4; ni++) {
            int n = n0w + ni * 8 + gq;
            uint2 b0 = Bs[cur][kq][n], b1 = Bs[cur][kq + 4][n];
            bh[ni][0] = b0.x; bh[ni][1] = b1.x;
            bl[ni][0] = b0.y; bl[ni][1] = b1.y;
        }
#pragma unroll
        for (int mi = 0; mi < 2; mi++)
#pragma unroll
            for (int ni = 0; ni < 4; ni++) {
                mma_bf16(acc[mi][ni], ah[mi], bh[ni]);
                mma_bf16(acc[mi][ni], al[mi], bh[ni]);
                mma_bf16(acc[mi][ni], ah[mi], bl[ni]);
            }

        if (more) store_tile(1 - cur);
        __syncthreads();
    }

    // epilogue
#pragma unroll
    for (int mi = 0; mi < 2; mi++)
#pragma unroll
        for (int ni = 0; ni < 4; ni++)
#pragma unroll
            for (int hf = 0; hf < 2; hf++) {
                int gm = m0 + m0w + mi * 16 + gq + hf * 8;
                if (gm >= M) continue;
                int gn = n0 + n0w + ni * 8 + kq * 2;
                float v0 = acc[mi][ni][hf * 2 + 0];
                float v1 = acc[mi][ni][hf * 2 + 1];
                bool ok0 = (gn < N), ok1 = (gn + 1 < N);
                if (MODE != 5 && bias) {
                    if (ok0) v0 += bias[gn];
                    if (ok1) v1 += bias[gn + 1];
                }
                if (MODE == 1) { v0 = fmaxf(v0, 0.f); v1 = fmaxf(v1, 0.f); }
                else if (MODE == 2) {
                    if (ok0) v0 += Cin[(size_t)gm * ldcin + gn];
                    if (ok1) v1 += Cin[(size_t)gm * ldcin + gn + 1];
                    v0 = fmaxf(v0, 0.f); v1 = fmaxf(v1, 0.f);
                } else if (MODE == 3) {
                    if (ok0) v0 = Cin[(size_t)gm * ldcin + gn] + fmaxf(v0, 0.f);
                    if (ok1) v1 = Cin[(size_t)gm * ldcin + gn + 1] + fmaxf(v1, 0.f);
                } else if (MODE == 5) {
                    float bb = bias[gm];
                    v0 += bb; v1 += bb;
                }
                if (ok0) C[(size_t)gm * ldc + gn]     = v0;
                if (ok1) C[(size_t)gm * ldc + gn + 1] = v1;
            }
}

// ---------------- host launch ----------------
extern "C" void kernel_launch(void* const* d_in, const int* in_sizes, int n_in,
                              void* d_out, int out_size) {
    const float* x      = (const float*)d_in[0];
    const float* w_freq = (const float*)d_in[1];
    const float* b_freq = (const float*)d_in[2];
    const float* w_all1 = (const float*)d_in[3];
    const float* b_all1 = (const float*)d_in[4];
    const float* w_all2 = (const float*)d_in[5];
    const float* b_all2 = (const float*)d_in[6];
    const float* w_time = (const float*)d_in[7];
    const float* b_time = (const float*)d_in[8];
    const float* w_chan = (const float*)d_in[9];
    const float* b_chan = (const float*)d_in[10];
    const float* w_proj = (const float*)d_in[11];
    const float* b_proj = (const float*)d_in[12];
    const int*   kptr   = (const int*)d_in[13];
    float* out = (float*)d_out;
    size_t half = (size_t)out_size / 2;

    float *basis45, *cosl, *sinl, *xt, *spec2, *filt, *h, *z1, *z, *t, *tT, *cm, *wprojT;
    float4* coef4; int* coefI;
    cudaGetSymbolAddress((void**)&basis45, g_basis45);
    cudaGetSymbolAddress((void**)&cosl, g_cosl);
    cudaGetSymbolAddress((void**)&sinl, g_sinl);
    cudaGetSymbolAddress((void**)&xt, g_xt);
    cudaGetSymbolAddress((void**)&spec2, g_spec2);
    cudaGetSymbolAddress((void**)&coef4, g_coef4);
    cudaGetSymbolAddress((void**)&coefI, g_coefI);
    cudaGetSymbolAddress((void**)&filt, g_filt);
    cudaGetSymbolAddress((void**)&h, g_h);
    cudaGetSymbolAddress((void**)&z1, g_z1);
    cudaGetSymbolAddress((void**)&z, g_z);
    cudaGetSymbolAddress((void**)&t, g_t);
    cudaGetSymbolAddress((void**)&tT, g_tT);
    cudaGetSymbolAddress((void**)&cm, g_cm);
    cudaGetSymbolAddress((void**)&wprojT, g_wprojT);

    dim3 tb(32, 8);

    // 0) twiddle LUTs + DFT45 half-spectrum basis; w_proj transpose (pad rows stay 0)
    fill_luts<<<(L2F * NB + 255) / 256, 256>>>(basis45, cosl, sinl);
    transpose_ld<<<dim3((PREDL + 31) / 32, H2 / 32, 1), tb>>>(w_proj, wprojT, H2, PREDL, H2);

    // 1) x (b,L,C) -> xt (b,C,L)
    transpose_batched<<<dim3(ENC / 32, (SEQL + 31) / 32, BATCH), tb>>>(x, xt, SEQL, ENC);

    // 2) stage-1 half-spectra (fp32, fused CT permutation)
    gemm_s1<<<NROWS / 8, 256>>>(xt, basis45, spec2);

    // 3) stage-2 combine + top-k -> coef packs
    combine_topk<<<NROWS, 128>>>(spec2, kptr, cosl, sinl, coef4, coefI);

    // 4) sparse rotation irfft -> filt
    reconstruct<<<NROWS, 256>>>(coef4, coefI, kptr, cosl, sinl, filt);

    // 5) residual = x - filt^T  -> first half of d_out
    transpose_sub<<<dim3((SEQL + 31) / 32, ENC / 32, BATCH), tb>>>(filt, x, out, SEQL, ENC);

    // 6) h = relu(filt @ w_freq + b_freq)   (N=64, K=720)
    gemm_bf<1><<<dim3(1, NROWS / 128), 256>>>(
        filt, SEQL, w_freq, H_FREQ, b_freq, nullptr, 0, h, H_FREQ,
        NROWS, H_FREQ, SEQL, 0, 0, 0, 0);

    // 7) z1 = h @ w_all1[0:64] + b_all1 ; then z1 = relu(xt @ w_all1[64:] + z1)
    gemm_bf<0><<<dim3(H1 / 64, NROWS / 128), 256>>>(
        h, H_FREQ, w_all1, H1, b_all1, nullptr, 0, z1, H1,
        NROWS, H1, H_FREQ, 0, 0, 0, 0);
    gemm_bf<2><<<dim3(H1 / 64, NROWS / 128), 256>>>(
        xt, SEQL, w_all1 + (size_t)H_FREQ * H1, H1, nullptr, z1, H1, z1, H1,
        NROWS, H1, SEQL, 0, 0, 0, 0);

    // 8) z = z1 @ w_all2 + b_all2
    gemm_bf<0><<<dim3(H2 / 64, NROWS / 128), 256>>>(
        z1, H1, w_all2, H2, b_all2, nullptr, 0, z, H2,
        NROWS, H2, H1, 0, 0, 0, 0);

    // 9) t = z + relu(z @ w_time + b_time)
    gemm_bf<3><<<dim3(H2 / 64, NROWS / 128), 256>>>(
        z, H2, w_time, H2, b_time, z, H2, t, H2,
        NROWS, H2, H2, 0, 0, 0, 0);

    // 10) t (b,C,H2) -> tT (b,H2,C)
    transpose_batched<<<dim3(H2 / 32, ENC / 32, BATCH), tb>>>(t, tT, ENC, H2);

    // 11) cm = tT + relu(tT @ w_chan + b_chan)   (rows = b*H2 = 16384, N=K=512)
    gemm_bf<3><<<dim3(ENC / 64, (BATCH * H2) / 128), 256>>>(
        tT, ENC, w_chan, ENC, b_chan, tT, ENC, cm, ENC,
        BATCH * H2, ENC, ENC, 0, 0, 0, 0);

    // 12) out2[b][l][i] = sum_h w_projT[l][h] * cm[b][h][i] + b_proj[l]
    //     batched over b, written DIRECTLY into d_out second half.
    gemm_bf<5><<<dim3(ENC / 64, PREDPAD / 128, BATCH), 256>>>(
        wprojT, H2, cm, ENC, b_proj, nullptr, 0, out + half, ENC,
        PREDL, ENC, H2, 0, (long)H2 * ENC, 0, (long)PREDL * ENC);
}

// round 15
// speedup vs baseline: 1.0303x; 1.0303x over previous
#include <cuda_runtime.h>
#include <cuda_bf16.h>
#include <cstdint>
#include <cstddef>

// ---------------- problem constants ----------------
#define BATCH   64
#define SEQL    720      // L = 16 * 45
#define ENC     512      // C
#define NROWS   (BATCH*ENC)       // 32768
#define NFREQ   361               // rfft bins
#define H_FREQ  64
#define H1      128
#define H2      256
#define PREDL   720
#define PREDPAD 768      // padded M for the output GEMM

#define L1F     16       // first CT factor
#define L2F     45       // second CT factor
#define NB      48       // stage-1 output width: [cos 0..22 | pad | -sin 0..22 | pad]

// ---------------- scratch (device globals; no allocs allowed) ----------------
__device__ float g_basis45[L2F*NB];           // DFT45 half-spectrum basis
__device__ float g_cosl[SEQL];
__device__ float g_sinl[SEQL];
__device__ float g_xt  [(size_t)NROWS*SEQL];  // x channel-major (b,c,l)
__device__ float g_spec2[(size_t)NROWS*L1F*NB]; // stage-1 partial half-spectra
__device__ float4 g_coef4[(size_t)NROWS*32];  // (re*w, im*w, twid.x, twid.y)
__device__ int    g_coefI[(size_t)NROWS*32];  // selected freq
__device__ float g_filt[(size_t)NROWS*SEQL];
__device__ float g_h   [(size_t)NROWS*H_FREQ];
__device__ float g_z1  [(size_t)NROWS*H1];
__device__ float g_z   [(size_t)NROWS*H2];
__device__ float g_t   [(size_t)NROWS*H2];
__device__ float g_tT  [(size_t)NROWS*H2];    // t transposed per batch (b,h,c)
__device__ float g_cm  [(size_t)NROWS*H2];    // channel-mixed (b,h,c)
__device__ float g_wprojT[(size_t)PREDPAD*H2]; // w_proj^T padded; pad rows stay 0

// ---------------- LUT / basis fill ----------------
__global__ void fill_luts(float* __restrict__ basis45, float* __restrict__ cosl,
                          float* __restrict__ sinl) {
    int idx = blockIdx.x * blockDim.x + threadIdx.x;
    if (idx < SEQL) {
        double s, c;
        sincospi((double)(2 * idx) / (double)SEQL, &s, &c);
        cosl[idx] = (float)c;
        sinl[idx] = (float)s;
    }
    if (idx < L2F * NB) {
        int l2 = idx / NB, c = idx % NB;
        float v = 0.f;
        if (c < 23 || (c >= 24 && c < 47)) {
            int g = (c < 23) ? c : (c - 24);
            int a = (g * l2) % L2F;
            double s, cc;
            sincospi((double)(2 * a) / (double)L2F, &s, &cc);
            v = (c < 23) ? (float)cc : (float)(-s);
        }
        basis45[idx] = v;
    }
}

// ---------------- batched transpose (B,R,C) -> (B,C,R) ----------------
__global__ void transpose_batched(const float* __restrict__ in, float* __restrict__ out,
                                  int R, int C) {
    __shared__ float tile[32][33];
    int b = blockIdx.z;
    int c0 = blockIdx.x * 32, r0 = blockIdx.y * 32;
    const float* pin = in + (size_t)b * R * C;
    float* pout = out + (size_t)b * R * C;
    int tx = threadIdx.x, ty = threadIdx.y;
#pragma unroll
    for (int j = 0; j < 32; j += 8) {
        int r = r0 + ty + j, c = c0 + tx;
        if (r < R && c < C) tile[ty + j][tx] = pin[(size_t)r * C + c];
    }
    __syncthreads();
#pragma unroll
    for (int j = 0; j < 32; j += 8) {
        int c = c0 + ty + j, r = r0 + tx;
        if (c < C && r < R) pout[(size_t)c * R + r] = tile[tx][ty + j];
    }
}

// variant writing into an output with row stride ldo (for padded w_projT)
__global__ void transpose_ld(const float* __restrict__ in, float* __restrict__ out,
                             int R, int C, int ldo) {
    __shared__ float tile[32][33];
    int c0 = blockIdx.x * 32, r0 = blockIdx.y * 32;
    int tx = threadIdx.x, ty = threadIdx.y;
#pragma unroll
    for (int j = 0; j < 32; j += 8) {
        int r = r0 + ty + j, c = c0 + tx;
        if (r < R && c < C) tile[ty + j][tx] = in[(size_t)r * C + c];
    }
    __syncthreads();
#pragma unroll
    for (int j = 0; j < 32; j += 8) {
        int c = c0 + ty + j, r = r0 + tx;
        if (c < C && r < R) out[(size_t)c * ldo + r] = tile[tx][ty + j];
    }
}

// src: (B,C,L) channel-major; out: (B,L,C); out = xin - src^T
__global__ void transpose_sub(const float* __restrict__ src, const float* __restrict__ xin,
                              float* __restrict__ out, int L, int C) {
    __shared__ float tile[32][33];
    int b = blockIdx.z;
    int l0 = blockIdx.x * 32, c0 = blockIdx.y * 32;
    const float* ps = src + (size_t)b * C * L;
#pragma unroll
    for (int j = 0; j < 32; j += 8) {
        int c = c0 + threadIdx.y + j, l = l0 + threadIdx.x;
        if (c < C && l < L) tile[threadIdx.y + j][threadIdx.x] = ps[(size_t)c * L + l];
    }
    __syncthreads();
    size_t ob = (size_t)b * L * C;
#pragma unroll
    for (int j = 0; j < 32; j += 8) {
        int l = l0 + threadIdx.y + j, c = c0 + threadIdx.x;
        if (l < L && c < C) {
            float v = tile[threadIdx.x][threadIdx.y + j];
            if (xin) v = xin[ob + (size_t)l * C + c] - v;
            out[ob + (size_t)l * C + c] = v;
        }
    }
}

// ------- stage-1: per-block 8 xt rows x full DFT45 half-spectrum (fp32) -------
__global__ void __launch_bounds__(256) gemm_s1(
    const float* __restrict__ xt, const float* __restrict__ basis,
    float* __restrict__ spec2) {
    __shared__ float Axt[8][SEQL];
    __shared__ float Bs[L2F][NB];
    const int tid = threadIdx.x;
    const size_t base = (size_t)blockIdx.x * (8 * SEQL);

    {
        const float4* src = reinterpret_cast<const float4*>(xt + base);
        float4* dst = reinterpret_cast<float4*>(&Axt[0][0]);
        for (int i = tid; i < 8 * SEQL / 4; i += 256) dst[i] = src[i];
    }
    {
        const float4* src = reinterpret_cast<const float4*>(basis);
        float4* dst = reinterpret_cast<float4*>(&Bs[0][0]);
        for (int i = tid; i < L2F * NB / 4; i += 256) dst[i] = src[i];
    }
    __syncthreads();

    const int tm = (tid >> 3) * 4;
    const int tn = (tid & 7) * 6;
    const int orig = tm >> 4;
    const int l1b = tm & 15;

    float acc[4][6] = {};
#pragma unroll 15
    for (int k = 0; k < L2F; k++) {
        float4 av = *reinterpret_cast<const float4*>(&Axt[orig][l1b + 16 * k]);
        float2 b0 = *reinterpret_cast<const float2*>(&Bs[k][tn]);
        float2 b1 = *reinterpret_cast<const float2*>(&Bs[k][tn + 2]);
        float2 b2 = *reinterpret_cast<const float2*>(&Bs[k][tn + 4]);
        float a[4] = {av.x, av.y, av.z, av.w};
        float b[6] = {b0.x, b0.y, b1.x, b1.y, b2.x, b2.y};
#pragma unroll
        for (int i = 0; i < 4; i++)
#pragma unroll
            for (int j = 0; j < 6; j++)
                acc[i][j] = fmaf(a[i], b[j], acc[i][j]);
    }

    size_t gmbase = (size_t)blockIdx.x * 128 + tm;
#pragma unroll
    for (int i = 0; i < 4; i++) {
        float* orow = spec2 + (gmbase + i) * NB + tn;
#pragma unroll
        for (int j = 0; j < 6; j += 2)
            *reinterpret_cast<float2*>(&orow[j]) = make_float2(acc[i][j], acc[i][j + 1]);
    }
}

// ------- stage-2 twiddle combine + per-row top-k selection -> coef packs -------
__global__ void __launch_bounds__(128) combine_topk(
    const float* __restrict__ spec2, const int* __restrict__ kptr,
    const float* __restrict__ cosl, const float* __restrict__ sinl,
    float4* __restrict__ coef4, int* __restrict__ coefI) {
    int row = blockIdx.x;
    const float* srow = spec2 + (size_t)row * (L1F * NB);

    __shared__ float2 slut[SEQL];
    __shared__ float2 sS2[L1F][23];
    __shared__ float sXre[NFREQ], sXim[NFREQ], sMag[NFREQ];

    int tid = threadIdx.x;
    for (int i = tid; i < SEQL; i += 128) slut[i] = make_float2(cosl[i], sinl[i]);
    for (int i = tid; i < L1F * 23; i += 128) {
        int l1 = i / 23, g = i % 23;
        sS2[l1][g] = make_float2(srow[l1 * NB + g], srow[l1 * NB + 24 + g]);
    }
    __syncthreads();

    for (int f = tid; f < NFREQ; f += 128) {
        int g = f % L2F;
        int gc = g; float sgn = 1.f;
        if (g >= 23) { gc = L2F - g; sgn = -1.f; }
        float xr = 0.f, xi = 0.f;
        int a = 0;
#pragma unroll
        for (int l1 = 0; l1 < L1F; l1++) {
            float2 w = slut[a];
            float2 s = sS2[l1][gc];
            float sr = s.x;
            float si = sgn * s.y;
            xr = fmaf(sr, w.x, fmaf(si, w.y, xr));
            xi = fmaf(si, w.x, fmaf(-sr, w.y, xi));
            a += f; if (a >= SEQL) a -= SEQL;
        }
        sXre[f] = xr; sXim[f] = xi;
        sMag[f] = xr * xr + xi * xi;
    }
    __syncthreads();

    if (tid < 32) {
        int lane = tid;
        float mag[12];
#pragma unroll
        for (int j = 0; j < 12; j++) {
            int idx = lane + 32 * j;
            mag[j] = (idx < NFREQ) ? sMag[idx] : -1.f;
        }
        int k = *kptr;
        if (k > 32) k = 32;
        if (k < 0) k = 0;
        const float scale = 1.f / (float)SEQL;
        for (int it = 0; it < k; it++) {
            float best = -1.f; int bslot = 0;
#pragma unroll
            for (int j = 0; j < 12; j++)
                if (mag[j] > best) { best = mag[j]; bslot = j; }
            int bidx = lane + 32 * bslot;
#pragma unroll
            for (int o = 16; o > 0; o >>= 1) {
                float ov = __shfl_xor_sync(0xffffffffu, best, o);
                int   oi = __shfl_xor_sync(0xffffffffu, bidx, o);
                if (ov > best || (ov == best && oi < bidx)) { best = ov; bidx = oi; }
            }
            if ((bidx & 31) == lane) {
                int j = bidx >> 5;
                float w = (bidx == 0 || bidx == NFREQ - 1) ? scale : 2.f * scale;
                float2 tw = slut[bidx];
                coef4[(size_t)row * 32 + it] =
                    make_float4(sXre[bidx] * w, sXim[bidx] * w, tw.x, tw.y);
                coefI[(size_t)row * 32 + it] = bidx;
                mag[j] = -2.f;
            }
        }
    }
}

// ------- sparse rotation irfft from coef packs -------
__global__ void __launch_bounds__(256) reconstruct(
    const float4* __restrict__ coef4, const int* __restrict__ coefI,
    const int* __restrict__ kptr,
    const float* __restrict__ cosl, const float* __restrict__ sinl,
    float* __restrict__ filt) {
    int row = blockIdx.x;
    __shared__ float2 slut[SEQL];
    __shared__ float4 sc[32];
    __shared__ int    sf[32];

    int tid = threadIdx.x;
    for (int i = tid; i < SEQL; i += 256) slut[i] = make_float2(cosl[i], sinl[i]);
    int k = *kptr;
    if (k > 32) k = 32;
    if (k < 0) k = 0;
    if (tid < k) {
        sc[tid] = coef4[(size_t)row * 32 + tid];
        sf[tid] = coefI[(size_t)row * 32 + tid];
    }
    __syncthreads();

    float* outp = filt + (size_t)row * SEQL;
    if (tid < 240) {
        int t0 = 3 * tid;
        float acc0 = 0.f, acc1 = 0.f, acc2 = 0.f;
        for (int j = 0; j < k; j++) {
            float4 c4 = sc[j];
            int f = sf[j];
            float r = c4.x, m = c4.y;
            int a0 = (f * t0) % SEQL;
            float2 p0 = slut[a0];
            acc0 = fmaf(r, p0.x, fmaf(-m, p0.y, acc0));
            float2 p1;
            p1.x = fmaf(-p0.y, c4.w, p0.x * c4.z);
            p1.y = fmaf(p0.x, c4.w, p0.y * c4.z);
            acc1 = fmaf(r, p1.x, fmaf(-m, p1.y, acc1));
            float2 p2;
            p2.x = fmaf(-p1.y, c4.w, p1.x * c4.z);
            p2.y = fmaf(p1.x, c4.w, p1.y * c4.z);
            acc2 = fmaf(r, p2.x, fmaf(-m, p2.y, acc2));
        }
        outp[t0 + 0] = acc0;
        outp[t0 + 1] = acc1;
        outp[t0 + 2] = acc2;
    }
}

// ---------------- bf16 helpers ----------------
__device__ __forceinline__ void split_pack_bf16(float e, float o, uint32_t& hi, uint32_t& lo) {
    __nv_bfloat16 he = __float2bfloat16_rn(e);
    __nv_bfloat16 ho = __float2bfloat16_rn(o);
    float re = e - __bfloat162float(he);
    float ro = o - __bfloat162float(ho);
    __nv_bfloat16 le = __float2bfloat16_rn(re);
    __nv_bfloat16 lo2 = __float2bfloat16_rn(ro);
    unsigned short ue = *reinterpret_cast<unsigned short*>(&he);
    unsigned short uo = *reinterpret_cast<unsigned short*>(&ho);
    unsigned short ve = *reinterpret_cast<unsigned short*>(&le);
    unsigned short vo = *reinterpret_cast<unsigned short*>(&lo2);
    hi = ((uint32_t)uo << 16) | ue;
    lo = ((uint32_t)vo << 16) | ve;
}

__device__ __forceinline__ void mma_bf16(float* d, const uint32_t* a, const uint32_t* b) {
    asm volatile(
        "mma.sync.aligned.m16n8k16.row.col.f32.bf16.bf16.f32 "
        "{%0,%1,%2,%3}, {%4,%5,%6,%7}, {%8,%9}, {%0,%1,%2,%3};\n"
        : "+f"(d[0]), "+f"(d[1]), "+f"(d[2]), "+f"(d[3])
        : "r"(a[0]), "r"(a[1]), "r"(a[2]), "r"(a[3]), "r"(b[0]), "r"(b[1]));
}

// ------- tensor-core GEMM: 128M x 64N block, bf16 3-term split, m16n8k16 -------
// SINGLE-buffered smem (round-12 proven mainloop). z-batched via strides.
// MODE 0: +bias[col] ; 1: relu ; 2: relu(+Cin) ; 3: Cin + relu ; 5: +bias[row]
// M guarded in epilogue (A rows up to padded extent must be readable).
template <int MODE>
__global__ void __launch_bounds__(256) gemm_bf(
    const float* __restrict__ A, int lda,
    const float* __restrict__ B, int ldb,
    const float* __restrict__ bias,
    const float* __restrict__ Cin, int ldcin,
    float* __restrict__ C, int ldc,
    int M, int N, int K,
    long zA, long zB, long zCin, long zC) {
    __shared__ uint2 As[8][140];   // [kp][m] (hi, lo)
    __shared__ uint2 Bs[8][76];    // [kp][n]

    const size_t zi = blockIdx.z;
    A += zi * zA; B += zi * zB;
    if (Cin) Cin += zi * zCin;
    C += zi * zC;

    const int tid = threadIdx.x;
    const int m0 = blockIdx.y * 128, n0 = blockIdx.x * 64;
    const int lane = tid & 31, warp = tid >> 5;
    const int wm = warp & 3, wn = warp >> 2;
    const int m0w = wm * 32, n0w = wn * 32;
    const int kq = lane & 3, gq = lane >> 2;

    const int arow = tid >> 1, ak = (tid & 1) * 8, akp = (tid & 1) * 4;
    const int bkp = tid >> 5, bn2 = (tid & 31) * 2;

    float acc[2][4][4];
#pragma unroll
    for (int i = 0; i < 2; i++)
#pragma unroll
        for (int j = 0; j < 4; j++)
#pragma unroll
            for (int q = 0; q < 4; q++) acc[i][j][q] = 0.f;

    // prefetch first tile
    float4 aP0 = *reinterpret_cast<const float4*>(&A[(size_t)(m0 + arow) * lda + ak]);
    float4 aP1 = *reinterpret_cast<const float4*>(&A[(size_t)(m0 + arow) * lda + ak + 4]);
    float be[2], bo[2];
    {
        const float* B0 = &B[(size_t)(2 * bkp) * ldb];
        const float* B1 = &B[(size_t)(2 * bkp + 1) * ldb];
#pragma unroll
        for (int i = 0; i < 2; i++) {
            int n = n0 + bn2 + i;
            be[i] = (n < N) ? B0[n] : 0.f;
            bo[i] = (n < N) ? B1[n] : 0.f;
        }
    }

    for (int k0 = 0; k0 < K; k0 += 16) {
        {
            float av[8] = {aP0.x, aP0.y, aP0.z, aP0.w, aP1.x, aP1.y, aP1.z, aP1.w};
#pragma unroll
            for (int i = 0; i < 4; i++) {
                uint32_t h, l;
                split_pack_bf16(av[2 * i], av[2 * i + 1], h, l);
                As[akp + i][arow] = make_uint2(h, l);
            }
#pragma unroll
            for (int i = 0; i < 2; i++) {
                uint32_t h, l;
                split_pack_bf16(be[i], bo[i], h, l);
                Bs[bkp][bn2 + i] = make_uint2(h, l);
            }
        }
        __syncthreads();

        if (k0 + 16 < K) {
            aP0 = *reinterpret_cast<const float4*>(&A[(size_t)(m0 + arow) * lda + (k0 + 16 + ak)]);
            aP1 = *reinterpret_cast<const float4*>(&A[(size_t)(m0 + arow) * lda + (k0 + 16 + ak + 4)]);
            const float* B0 = &B[(size_t)(k0 + 16 + 2 * bkp) * ldb];
            const float* B1 = &B[(size_t)(k0 + 16 + 2 * bkp + 1) * ldb];
#pragma unroll
            for (int i = 0; i < 2; i++) {
                int n = n0 + bn2 + i;
                be[i] = (n < N) ? B0[n] : 0.f;
                bo[i] = (n < N) ? B1[n] : 0.f;
            }
        }

        // one k16 MMA sweep
        uint32_t ah[2][4], al[2][4], bh[4][2], bl[4][2];
#pragma unroll
        for (int mi = 0; mi < 2; mi++) {
            int m = m0w + mi * 16 + gq;
            uint2 a00 = As[kq][m],     a01 = As[kq][m + 8];
            uint2 a10 = As[kq + 4][m], a11 = As[kq + 4][m + 8];
            ah[mi][0] = a00.x; ah[mi][1] = a01.x; ah[mi][2] = a10.x; ah[mi][3] = a11.x;
            al[mi][0] = a00.y; al[mi][1] = a01.y; al[mi][2] = a10.y; al[mi][3] = a11.y;
        }
#pragma unroll
        for (int ni = 0; ni < 4; ni++) {
            int n = n0w + ni * 8 + gq;
            uint2 b0 = Bs[kq][n], b1 = Bs[kq + 4][n];
            bh[ni][0] = b0.x; bh[ni][1] = b1.x;
            bl[ni][0] = b0.y; bl[ni][1] = b1.y;
        }
#pragma unroll
        for (int mi = 0; mi < 2; mi++)
#pragma unroll
            for (int ni = 0; ni < 4; ni++) {
                mma_bf16(acc[mi][ni], ah[mi], bh[ni]);
                mma_bf16(acc[mi][ni], al[mi], bh[ni]);
                mma_bf16(acc[mi][ni], ah[mi], bl[ni]);
            }
        __syncthreads();
    }

    // epilogue
#pragma unroll
    for (int mi = 0; mi < 2; mi++)
#pragma unroll
        for (int ni = 0; ni < 4; ni++)
#pragma unroll
            for (int hf = 0; hf < 2; hf++) {
                int gm = m0 + m0w + mi * 16 + gq + hf * 8;
                if (gm >= M) continue;
                int gn = n0 + n0w + ni * 8 + kq * 2;
                float v0 = acc[mi][ni][hf * 2 + 0];
                float v1 = acc[mi][ni][hf * 2 + 1];
                bool ok0 = (gn < N), ok1 = (gn + 1 < N);
                if (MODE != 5 && bias) {
                    if (ok0) v0 += bias[gn];
                    if (ok1) v1 += bias[gn + 1];
                }
                if (MODE == 1) { v0 = fmaxf(v0, 0.f); v1 = fmaxf(v1, 0.f); }
                else if (MODE == 2) {
                    if (ok0) v0 += Cin[(size_t)gm * ldcin + gn];
                    if (ok1) v1 += Cin[(size_t)gm * ldcin + gn + 1];
                    v0 = fmaxf(v0, 0.f); v1 = fmaxf(v1, 0.f);
                } else if (MODE == 3) {
                    if (ok0) v0 = Cin[(size_t)gm * ldcin + gn] + fmaxf(v0, 0.f);
                    if (ok1) v1 = Cin[(size_t)gm * ldcin + gn + 1] + fmaxf(v1, 0.f);
                } else if (MODE == 5) {
                    float bb = bias[gm];
                    v0 += bb; v1 += bb;
                }
                if (ok0) C[(size_t)gm * ldc + gn]     = v0;
                if (ok1) C[(size_t)gm * ldc + gn + 1] = v1;
            }
}

// ---------------- host launch ----------------
extern "C" void kernel_launch(void* const* d_in, const int* in_sizes, int n_in,
                              void* d_out, int out_size) {
    const float* x      = (const float*)d_in[0];
    const float* w_freq = (const float*)d_in[1];
    const float* b_freq = (const float*)d_in[2];
    const float* w_all1 = (const float*)d_in[3];
    const float* b_all1 = (const float*)d_in[4];
    const float* w_all2 = (const float*)d_in[5];
    const float* b_all2 = (const float*)d_in[6];
    const float* w_time = (const float*)d_in[7];
    const float* b_time = (const float*)d_in[8];
    const float* w_chan = (const float*)d_in[9];
    const float* b_chan = (const float*)d_in[10];
    const float* w_proj = (const float*)d_in[11];
    const float* b_proj = (const float*)d_in[12];
    const int*   kptr   = (const int*)d_in[13];
    float* out = (float*)d_out;
    size_t half = (size_t)out_size / 2;

    float *basis45, *cosl, *sinl, *xt, *spec2, *filt, *h, *z1, *z, *t, *tT, *cm, *wprojT;
    float4* coef4; int* coefI;
    cudaGetSymbolAddress((void**)&basis45, g_basis45);
    cudaGetSymbolAddress((void**)&cosl, g_cosl);
    cudaGetSymbolAddress((void**)&sinl, g_sinl);
    cudaGetSymbolAddress((void**)&xt, g_xt);
    cudaGetSymbolAddress((void**)&spec2, g_spec2);
    cudaGetSymbolAddress((void**)&coef4, g_coef4);
    cudaGetSymbolAddress((void**)&coefI, g_coefI);
    cudaGetSymbolAddress((void**)&filt, g_filt);
    cudaGetSymbolAddress((void**)&h, g_h);
    cudaGetSymbolAddress((void**)&z1, g_z1);
    cudaGetSymbolAddress((void**)&z, g_z);
    cudaGetSymbolAddress((void**)&t, g_t);
    cudaGetSymbolAddress((void**)&tT, g_tT);
    cudaGetSymbolAddress((void**)&cm, g_cm);
    cudaGetSymbolAddress((void**)&wprojT, g_wprojT);

    dim3 tb(32, 8);

    // 0) twiddle LUTs + DFT45 half-spectrum basis; w_proj transpose (pad rows stay 0)
    fill_luts<<<(L2F * NB + 255) / 256, 256>>>(basis45, cosl, sinl);
    transpose_ld<<<dim3((PREDL + 31) / 32, H2 / 32, 1), tb>>>(w_proj, wprojT, H2, PREDL, H2);

    // 1) x (b,L,C) -> xt (b,C,L)
    transpose_batched<<<dim3(ENC / 32, (SEQL + 31) / 32, BATCH), tb>>>(x, xt, SEQL, ENC);

    // 2) stage-1 half-spectra (fp32, fused CT permutation)
    gemm_s1<<<NROWS / 8, 256>>>(xt, basis45, spec2);

    // 3) stage-2 combine + top-k -> coef packs
    combine_topk<<<NROWS, 128>>>(spec2, kptr, cosl, sinl, coef4, coefI);

    // 4) sparse rotation irfft -> filt
    reconstruct<<<NROWS, 256>>>(coef4, coefI, kptr, cosl, sinl, filt);

    // 5) residual = x - filt^T  -> first half of d_out
    transpose_sub<<<dim3((SEQL + 31) / 32, ENC / 32, BATCH), tb>>>(filt, x, out, SEQL, ENC);

    // 6) h = relu(filt @ w_freq + b_freq)   (N=64, K=720)
    gemm_bf<1><<<dim3(1, NROWS / 128), 256>>>(
        filt, SEQL, w_freq, H_FREQ, b_freq, nullptr, 0, h, H_FREQ,
        NROWS, H_FREQ, SEQL, 0, 0, 0, 0);

    // 7) z1 = h @ w_all1[0:64] + b_all1 ; then z1 = relu(xt @ w_all1[64:] + z1)
    gemm_bf<0><<<dim3(H1 / 64, NROWS / 128), 256>>>(
        h, H_FREQ, w_all1, H1, b_all1, nullptr, 0, z1, H1,
        NROWS, H1, H_FREQ, 0, 0, 0, 0);
    gemm_bf<2><<<dim3(H1 / 64, NROWS / 128), 256>>>(
        xt, SEQL, w_all1 + (size_t)H_FREQ * H1, H1, nullptr, z1, H1, z1, H1,
        NROWS, H1, SEQL, 0, 0, 0, 0);

    // 8) z = z1 @ w_all2 + b_all2
    gemm_bf<0><<<dim3(H2 / 64, NROWS / 128), 256>>>(
        z1, H1, w_all2, H2, b_all2, nullptr, 0, z, H2,
        NROWS, H2, H1, 0, 0, 0, 0);

    // 9) t = z + relu(z @ w_time + b_time)
    gemm_bf<3><<<dim3(H2 / 64, NROWS / 128), 256>>>(
        z, H2, w_time, H2, b_time, z, H2, t, H2,
        NROWS, H2, H2, 0, 0, 0, 0);

    // 10) t (b,C,H2) -> tT (b,H2,C)
    transpose_batched<<<dim3(H2 / 32, ENC / 32, BATCH), tb>>>(t, tT, ENC, H2);

    // 11) cm = tT + relu(tT @ w_chan + b_chan)   (rows = b*H2 = 16384, N=K=512)
    gemm_bf<3><<<dim3(ENC / 64, (BATCH * H2) / 128), 256>>>(
        tT, ENC, w_chan, ENC, b_chan, tT, ENC, cm, ENC,
        BATCH * H2, ENC, ENC, 0, 0, 0, 0);

    // 12) out2[b][l][i] = sum_h w_projT[l][h] * cm[b][h][i] + b_proj[l]
    //     batched over b, written DIRECTLY into d_out second half.
    gemm_bf<5><<<dim3(ENC / 64, PREDPAD / 128, BATCH), 256>>>(
        wprojT, H2, cm, ENC, b_proj, nullptr, 0, out + half, ENC,
        PREDL, ENC, H2, 0, (long)H2 * ENC, 0, (long)PREDL * ENC);
}

// round 16
// speedup vs baseline: 1.0541x; 1.0231x over previous
#include <cuda_runtime.h>
#include <cuda_bf16.h>
#include <cstdint>
#include <cstddef>

// ---------------- problem constants ----------------
#define BATCH   64
#define SEQL    720      // L = 16 * 45
#define ENC     512      // C
#define NROWS   (BATCH*ENC)       // 32768
#define NFREQ   361               // rfft bins
#define H_FREQ  64
#define H1      128
#define H2      256
#define PREDL   720
#define PREDPAD 768      // padded M for the output GEMM

#define L1F     16       // first CT factor
#define L2F     45       // second CT factor
#define NB      48       // stage-1 output width: [cos 0..22 | pad | -sin 0..22 | pad]
#define RCH     8        // channels per reconstruct_residual block

// ---------------- scratch (device globals; no allocs allowed) ----------------
__device__ float g_basis45[L2F*NB];           // DFT45 half-spectrum basis
__device__ float g_cosl[SEQL];
__device__ float g_sinl[SEQL];
__device__ float g_xt  [(size_t)NROWS*SEQL];  // x channel-major (b,c,l)
__device__ float g_spec2[(size_t)NROWS*L1F*NB]; // stage-1 partial half-spectra
__device__ float4 g_coef4[(size_t)NROWS*32];  // (re*w, im*w, twid.x, twid.y)
__device__ int    g_coefI[(size_t)NROWS*32];  // selected freq
__device__ float g_filt[(size_t)NROWS*SEQL];
__device__ float g_h   [(size_t)NROWS*H_FREQ];
__device__ float g_z1  [(size_t)NROWS*H1];
__device__ float g_z   [(size_t)NROWS*H2];
__device__ float g_t   [(size_t)NROWS*H2];
__device__ float g_tT  [(size_t)NROWS*H2];    // t transposed per batch (b,h,c)
__device__ float g_cm  [(size_t)NROWS*H2];    // channel-mixed (b,h,c)
__device__ float g_wprojT[(size_t)PREDPAD*H2]; // w_proj^T padded; pad rows stay 0

// ---------------- LUT / basis fill ----------------
__global__ void fill_luts(float* __restrict__ basis45, float* __restrict__ cosl,
                          float* __restrict__ sinl) {
    int idx = blockIdx.x * blockDim.x + threadIdx.x;
    if (idx < SEQL) {
        double s, c;
        sincospi((double)(2 * idx) / (double)SEQL, &s, &c);
        cosl[idx] = (float)c;
        sinl[idx] = (float)s;
    }
    if (idx < L2F * NB) {
        int l2 = idx / NB, c = idx % NB;
        float v = 0.f;
        if (c < 23 || (c >= 24 && c < 47)) {
            int g = (c < 23) ? c : (c - 24);
            int a = (g * l2) % L2F;
            double s, cc;
            sincospi((double)(2 * a) / (double)L2F, &s, &cc);
            v = (c < 23) ? (float)cc : (float)(-s);
        }
        basis45[idx] = v;
    }
}

// ---------------- batched transpose (B,R,C) -> (B,C,R) ----------------
__global__ void transpose_batched(const float* __restrict__ in, float* __restrict__ out,
                                  int R, int C) {
    __shared__ float tile[32][33];
    int b = blockIdx.z;
    int c0 = blockIdx.x * 32, r0 = blockIdx.y * 32;
    const float* pin = in + (size_t)b * R * C;
    float* pout = out + (size_t)b * R * C;
    int tx = threadIdx.x, ty = threadIdx.y;
#pragma unroll
    for (int j = 0; j < 32; j += 8) {
        int r = r0 + ty + j, c = c0 + tx;
        if (r < R && c < C) tile[ty + j][tx] = pin[(size_t)r * C + c];
    }
    __syncthreads();
#pragma unroll
    for (int j = 0; j < 32; j += 8) {
        int c = c0 + ty + j, r = r0 + tx;
        if (c < C && r < R) pout[(size_t)c * R + r] = tile[tx][ty + j];
    }
}

// variant writing into an output with row stride ldo (for padded w_projT)
__global__ void transpose_ld(const float* __restrict__ in, float* __restrict__ out,
                             int R, int C, int ldo) {
    __shared__ float tile[32][33];
    int c0 = blockIdx.x * 32, r0 = blockIdx.y * 32;
    int tx = threadIdx.x, ty = threadIdx.y;
#pragma unroll
    for (int j = 0; j < 32; j += 8) {
        int r = r0 + ty + j, c = c0 + tx;
        if (r < R && c < C) tile[ty + j][tx] = in[(size_t)r * C + c];
    }
    __syncthreads();
#pragma unroll
    for (int j = 0; j < 32; j += 8) {
        int c = c0 + ty + j, r = r0 + tx;
        if (c < C && r < R) out[(size_t)c * ldo + r] = tile[tx][ty + j];
    }
}

// ------- stage-1: per-block 8 xt rows x full DFT45 half-spectrum (fp32) -------
__global__ void __launch_bounds__(256) gemm_s1(
    const float* __restrict__ xt, const float* __restrict__ basis,
    float* __restrict__ spec2) {
    __shared__ float Axt[8][SEQL];
    __shared__ float Bs[L2F][NB];
    const int tid = threadIdx.x;
    const size_t base = (size_t)blockIdx.x * (8 * SEQL);

    {
        const float4* src = reinterpret_cast<const float4*>(xt + base);
        float4* dst = reinterpret_cast<float4*>(&Axt[0][0]);
        for (int i = tid; i < 8 * SEQL / 4; i += 256) dst[i] = src[i];
    }
    {
        const float4* src = reinterpret_cast<const float4*>(basis);
        float4* dst = reinterpret_cast<float4*>(&Bs[0][0]);
        for (int i = tid; i < L2F * NB / 4; i += 256) dst[i] = src[i];
    }
    __syncthreads();

    const int tm = (tid >> 3) * 4;
    const int tn = (tid & 7) * 6;
    const int orig = tm >> 4;
    const int l1b = tm & 15;

    float acc[4][6] = {};
#pragma unroll 15
    for (int k = 0; k < L2F; k++) {
        float4 av = *reinterpret_cast<const float4*>(&Axt[orig][l1b + 16 * k]);
        float2 b0 = *reinterpret_cast<const float2*>(&Bs[k][tn]);
        float2 b1 = *reinterpret_cast<const float2*>(&Bs[k][tn + 2]);
        float2 b2 = *reinterpret_cast<const float2*>(&Bs[k][tn + 4]);
        float a[4] = {av.x, av.y, av.z, av.w};
        float b[6] = {b0.x, b0.y, b1.x, b1.y, b2.x, b2.y};
#pragma unroll
        for (int i = 0; i < 4; i++)
#pragma unroll
            for (int j = 0; j < 6; j++)
                acc[i][j] = fmaf(a[i], b[j], acc[i][j]);
    }

    size_t gmbase = (size_t)blockIdx.x * 128 + tm;
#pragma unroll
    for (int i = 0; i < 4; i++) {
        float* orow = spec2 + (gmbase + i) * NB + tn;
#pragma unroll
        for (int j = 0; j < 6; j += 2)
            *reinterpret_cast<float2*>(&orow[j]) = make_float2(acc[i][j], acc[i][j + 1]);
    }
}

// ------- stage-2 twiddle combine + per-row top-k selection -> coef packs -------
__global__ void __launch_bounds__(128) combine_topk(
    const float* __restrict__ spec2, const int* __restrict__ kptr,
    const float* __restrict__ cosl, const float* __restrict__ sinl,
    float4* __restrict__ coef4, int* __restrict__ coefI) {
    int row = blockIdx.x;
    const float* srow = spec2 + (size_t)row * (L1F * NB);

    __shared__ float2 slut[SEQL];
    __shared__ float2 sS2[L1F][23];
    __shared__ float sXre[NFREQ], sXim[NFREQ], sMag[NFREQ];

    int tid = threadIdx.x;
    for (int i = tid; i < SEQL; i += 128) slut[i] = make_float2(cosl[i], sinl[i]);
    for (int i = tid; i < L1F * 23; i += 128) {
        int l1 = i / 23, g = i % 23;
        sS2[l1][g] = make_float2(srow[l1 * NB + g], srow[l1 * NB + 24 + g]);
    }
    __syncthreads();

    for (int f = tid; f < NFREQ; f += 128) {
        int g = f % L2F;
        int gc = g; float sgn = 1.f;
        if (g >= 23) { gc = L2F - g; sgn = -1.f; }
        float xr = 0.f, xi = 0.f;
        int a = 0;
#pragma unroll
        for (int l1 = 0; l1 < L1F; l1++) {
            float2 w = slut[a];
            float2 s = sS2[l1][gc];
            float sr = s.x;
            float si = sgn * s.y;
            xr = fmaf(sr, w.x, fmaf(si, w.y, xr));
            xi = fmaf(si, w.x, fmaf(-sr, w.y, xi));
            a += f; if (a >= SEQL) a -= SEQL;
        }
        sXre[f] = xr; sXim[f] = xi;
        sMag[f] = xr * xr + xi * xi;
    }
    __syncthreads();

    if (tid < 32) {
        int lane = tid;
        float mag[12];
#pragma unroll
        for (int j = 0; j < 12; j++) {
            int idx = lane + 32 * j;
            mag[j] = (idx < NFREQ) ? sMag[idx] : -1.f;
        }
        int k = *kptr;
        if (k > 32) k = 32;
        if (k < 0) k = 0;
        const float scale = 1.f / (float)SEQL;
        for (int it = 0; it < k; it++) {
            float best = -1.f; int bslot = 0;
#pragma unroll
            for (int j = 0; j < 12; j++)
                if (mag[j] > best) { best = mag[j]; bslot = j; }
            int bidx = lane + 32 * bslot;
#pragma unroll
            for (int o = 16; o > 0; o >>= 1) {
                float ov = __shfl_xor_sync(0xffffffffu, best, o);
                int   oi = __shfl_xor_sync(0xffffffffu, bidx, o);
                if (ov > best || (ov == best && oi < bidx)) { best = ov; bidx = oi; }
            }
            if ((bidx & 31) == lane) {
                int j = bidx >> 5;
                float w = (bidx == 0 || bidx == NFREQ - 1) ? scale : 2.f * scale;
                float2 tw = slut[bidx];
                coef4[(size_t)row * 32 + it] =
                    make_float4(sXre[bidx] * w, sXim[bidx] * w, tw.x, tw.y);
                coefI[(size_t)row * 32 + it] = bidx;
                mag[j] = -2.f;
            }
        }
    }
}

// ------- fused: sparse rotation irfft + filt write + residual (x - filt^T) -------
// Block = RCH consecutive channels of one batch. Per-channel math is IDENTICAL
// to the previous reconstruct kernel (same per-thread l-runs, same FMA order).
__global__ void __launch_bounds__(256) reconstruct_residual(
    const float4* __restrict__ coef4, const int* __restrict__ coefI,
    const int* __restrict__ kptr,
    const float* __restrict__ cosl, const float* __restrict__ sinl,
    const float* __restrict__ x,
    float* __restrict__ filt, float* __restrict__ outres) {
    __shared__ float2 slut[SEQL];
    __shared__ float4 sc[RCH][32];
    __shared__ int    sf[RCH][32];
    __shared__ float  sfilt[RCH][SEQL + 1];   // 721 stride: spreads banks

    int tid = threadIdx.x;
    int b = blockIdx.x >> 6;                  // ENC/RCH = 64 blocks per batch
    int cblk = blockIdx.x & 63;
    size_t row0 = (size_t)b * ENC + (size_t)cblk * RCH;

    for (int i = tid; i < SEQL; i += 256) slut[i] = make_float2(cosl[i], sinl[i]);
    int k = *kptr;
    if (k > 32) k = 32;
    if (k < 0) k = 0;
    for (int i = tid; i < RCH * 32; i += 256) {
        int ch = i >> 5, j = i & 31;
        if (j < k) {
            sc[ch][j] = coef4[(row0 + ch) * 32 + j];
            sf[ch][j] = coefI[(row0 + ch) * 32 + j];
        }
    }
    __syncthreads();

    if (tid < 240) {
        int t0 = 3 * tid;
#pragma unroll
        for (int ch = 0; ch < RCH; ch++) {
            float acc0 = 0.f, acc1 = 0.f, acc2 = 0.f;
            for (int j = 0; j < k; j++) {
                float4 c4 = sc[ch][j];
                int f = sf[ch][j];
                float r = c4.x, m = c4.y;
                int a0 = (f * t0) % SEQL;
                float2 p0 = slut[a0];
                acc0 = fmaf(r, p0.x, fmaf(-m, p0.y, acc0));
                float2 p1;
                p1.x = fmaf(-p0.y, c4.w, p0.x * c4.z);
                p1.y = fmaf(p0.x, c4.w, p0.y * c4.z);
                acc1 = fmaf(r, p1.x, fmaf(-m, p1.y, acc1));
                float2 p2;
                p2.x = fmaf(-p1.y, c4.w, p1.x * c4.z);
                p2.y = fmaf(p1.x, c4.w, p1.y * c4.z);
                acc2 = fmaf(r, p2.x, fmaf(-m, p2.y, acc2));
            }
            sfilt[ch][t0 + 0] = acc0;
            sfilt[ch][t0 + 1] = acc1;
            sfilt[ch][t0 + 2] = acc2;
        }
    }
    __syncthreads();

    // write filt (b,c,l) coalesced -- consumed by the MLPfreq GEMM
    float* fp = filt + row0 * SEQL;
#pragma unroll
    for (int ch = 0; ch < RCH; ch++)
        for (int l = tid; l < SEQL; l += 256)
            fp[(size_t)ch * SEQL + l] = sfilt[ch][l];

    // residual out[b][l][c0+j] = x[b][l][c0+j] - filt[c0+j][l]
    const float* xb = x + (size_t)b * SEQL * ENC + (size_t)cblk * RCH;
    float* ob = outres + (size_t)b * SEQL * ENC + (size_t)cblk * RCH;
    for (int i = tid; i < SEQL * RCH; i += 256) {
        int l = i >> 3, j = i & 7;
        ob[(size_t)l * ENC + j] = xb[(size_t)l * ENC + j] - sfilt[j][l];
    }
}

// ---------------- bf16 helpers ----------------
__device__ __forceinline__ void split_pack_bf16(float e, float o, uint32_t& hi, uint32_t& lo) {
    __nv_bfloat16 he = __float2bfloat16_rn(e);
    __nv_bfloat16 ho = __float2bfloat16_rn(o);
    float re = e - __bfloat162float(he);
    float ro = o - __bfloat162float(ho);
    __nv_bfloat16 le = __float2bfloat16_rn(re);
    __nv_bfloat16 lo2 = __float2bfloat16_rn(ro);
    unsigned short ue = *reinterpret_cast<unsigned short*>(&he);
    unsigned short uo = *reinterpret_cast<unsigned short*>(&ho);
    unsigned short ve = *reinterpret_cast<unsigned short*>(&le);
    unsigned short vo = *reinterpret_cast<unsigned short*>(&lo2);
    hi = ((uint32_t)uo << 16) | ue;
    lo = ((uint32_t)vo << 16) | ve;
}

__device__ __forceinline__ void mma_bf16(float* d, const uint32_t* a, const uint32_t* b) {
    asm volatile(
        "mma.sync.aligned.m16n8k16.row.col.f32.bf16.bf16.f32 "
        "{%0,%1,%2,%3}, {%4,%5,%6,%7}, {%8,%9}, {%0,%1,%2,%3};\n"
        : "+f"(d[0]), "+f"(d[1]), "+f"(d[2]), "+f"(d[3])
        : "r"(a[0]), "r"(a[1]), "r"(a[2]), "r"(a[3]), "r"(b[0]), "r"(b[1]));
}

// ------- tensor-core GEMM: 128M x 64N block, bf16 3-term split, m16n8k16 -------
// SINGLE-buffered smem (proven mainloop). z-batched via strides.
// MODE 0: +bias[col] ; 1: relu ; 2: relu(+Cin) ; 3: Cin + relu ; 5: +bias[row]
template <int MODE>
__global__ void __launch_bounds__(256) gemm_bf(
    const float* __restrict__ A, int lda,
    const float* __restrict__ B, int ldb,
    const float* __restrict__ bias,
    const float* __restrict__ Cin, int ldcin,
    float* __restrict__ C, int ldc,
    int M, int N, int K,
    long zA, long zB, long zCin, long zC) {
    __shared__ uint2 As[8][140];   // [kp][m] (hi, lo)
    __shared__ uint2 Bs[8][76];    // [kp][n]

    const size_t zi = blockIdx.z;
    A += zi * zA; B += zi * zB;
    if (Cin) Cin += zi * zCin;
    C += zi * zC;

    const int tid = threadIdx.x;
    const int m0 = blockIdx.y * 128, n0 = blockIdx.x * 64;
    const int lane = tid & 31, warp = tid >> 5;
    const int wm = warp & 3, wn = warp >> 2;
    const int m0w = wm * 32, n0w = wn * 32;
    const int kq = lane & 3, gq = lane >> 2;

    const int arow = tid >> 1, ak = (tid & 1) * 8, akp = (tid & 1) * 4;
    const int bkp = tid >> 5, bn2 = (tid & 31) * 2;

    float acc[2][4][4];
#pragma unroll
    for (int i = 0; i < 2; i++)
#pragma unroll
        for (int j = 0; j < 4; j++)
#pragma unroll
            for (int q = 0; q < 4; q++) acc[i][j][q] = 0.f;

    // prefetch first tile
    float4 aP0 = *reinterpret_cast<const float4*>(&A[(size_t)(m0 + arow) * lda + ak]);
    float4 aP1 = *reinterpret_cast<const float4*>(&A[(size_t)(m0 + arow) * lda + ak + 4]);
    float be[2], bo[2];
    {
        const float* B0 = &B[(size_t)(2 * bkp) * ldb];
        const float* B1 = &B[(size_t)(2 * bkp + 1) * ldb];
#pragma unroll
        for (int i = 0; i < 2; i++) {
            int n = n0 + bn2 + i;
            be[i] = (n < N) ? B0[n] : 0.f;
            bo[i] = (n < N) ? B1[n] : 0.f;
        }
    }

    for (int k0 = 0; k0 < K; k0 += 16) {
        {
            float av[8] = {aP0.x, aP0.y, aP0.z, aP0.w, aP1.x, aP1.y, aP1.z, aP1.w};
#pragma unroll
            for (int i = 0; i < 4; i++) {
                uint32_t h, l;
                split_pack_bf16(av[2 * i], av[2 * i + 1], h, l);
                As[akp + i][arow] = make_uint2(h, l);
            }
#pragma unroll
            for (int i = 0; i < 2; i++) {
                uint32_t h, l;
                split_pack_bf16(be[i], bo[i], h, l);
                Bs[bkp][bn2 + i] = make_uint2(h, l);
            }
        }
        __syncthreads();

        if (k0 + 16 < K) {
            aP0 = *reinterpret_cast<const float4*>(&A[(size_t)(m0 + arow) * lda + (k0 + 16 + ak)]);
            aP1 = *reinterpret_cast<const float4*>(&A[(size_t)(m0 + arow) * lda + (k0 + 16 + ak + 4)]);
            const float* B0 = &B[(size_t)(k0 + 16 + 2 * bkp) * ldb];
            const float* B1 = &B[(size_t)(k0 + 16 + 2 * bkp + 1) * ldb];
#pragma unroll
            for (int i = 0; i < 2; i++) {
                int n = n0 + bn2 + i;
                be[i] = (n < N) ? B0[n] : 0.f;
                bo[i] = (n < N) ? B1[n] : 0.f;
            }
        }

        // one k16 MMA sweep
        uint32_t ah[2][4], al[2][4], bh[4][2], bl[4][2];
#pragma unroll
        for (int mi = 0; mi < 2; mi++) {
            int m = m0w + mi * 16 + gq;
            uint2 a00 = As[kq][m],     a01 = As[kq][m + 8];
            uint2 a10 = As[kq + 4][m], a11 = As[kq + 4][m + 8];
            ah[mi][0] = a00.x; ah[mi][1] = a01.x; ah[mi][2] = a10.x; ah[mi][3] = a11.x;
            al[mi][0] = a00.y; al[mi][1] = a01.y; al[mi][2] = a10.y; al[mi][3] = a11.y;
        }
#pragma unroll
        for (int ni = 0; ni < 4; ni++) {
            int n = n0w + ni * 8 + gq;
            uint2 b0 = Bs[kq][n], b1 = Bs[kq + 4][n];
            bh[ni][0] = b0.x; bh[ni][1] = b1.x;
            bl[ni][0] = b0.y; bl[ni][1] = b1.y;
        }
#pragma unroll
        for (int mi = 0; mi < 2; mi++)
#pragma unroll
            for (int ni = 0; ni < 4; ni++) {
                mma_bf16(acc[mi][ni], ah[mi], bh[ni]);
                mma_bf16(acc[mi][ni], al[mi], bh[ni]);
                mma_bf16(acc[mi][ni], ah[mi], bl[ni]);
            }
        __syncthreads();
    }

    // epilogue
#pragma unroll
    for (int mi = 0; mi < 2; mi++)
#pragma unroll
        for (int ni = 0; ni < 4; ni++)
#pragma unroll
            for (int hf = 0; hf < 2; hf++) {
                int gm = m0 + m0w + mi * 16 + gq + hf * 8;
                if (gm >= M) continue;
                int gn = n0 + n0w + ni * 8 + kq * 2;
                float v0 = acc[mi][ni][hf * 2 + 0];
                float v1 = acc[mi][ni][hf * 2 + 1];
                bool ok0 = (gn < N), ok1 = (gn + 1 < N);
                if (MODE != 5 && bias) {
                    if (ok0) v0 += bias[gn];
                    if (ok1) v1 += bias[gn + 1];
                }
                if (MODE == 1) { v0 = fmaxf(v0, 0.f); v1 = fmaxf(v1, 0.f); }
                else if (MODE == 2) {
                    if (ok0) v0 += Cin[(size_t)gm * ldcin + gn];
                    if (ok1) v1 += Cin[(size_t)gm * ldcin + gn + 1];
                    v0 = fmaxf(v0, 0.f); v1 = fmaxf(v1, 0.f);
                } else if (MODE == 3) {
                    if (ok0) v0 = Cin[(size_t)gm * ldcin + gn] + fmaxf(v0, 0.f);
                    if (ok1) v1 = Cin[(size_t)gm * ldcin + gn + 1] + fmaxf(v1, 0.f);
                } else if (MODE == 5) {
                    float bb = bias[gm];
                    v0 += bb; v1 += bb;
                }
                if (ok0) C[(size_t)gm * ldc + gn]     = v0;
                if (ok1) C[(size_t)gm * ldc + gn + 1] = v1;
            }
}

// ---------------- host launch ----------------
extern "C" void kernel_launch(void* const* d_in, const int* in_sizes, int n_in,
                              void* d_out, int out_size) {
    const float* x      = (const float*)d_in[0];
    const float* w_freq = (const float*)d_in[1];
    const float* b_freq = (const float*)d_in[2];
    const float* w_all1 = (const float*)d_in[3];
    const float* b_all1 = (const float*)d_in[4];
    const float* w_all2 = (const float*)d_in[5];
    const float* b_all2 = (const float*)d_in[6];
    const float* w_time = (const float*)d_in[7];
    const float* b_time = (const float*)d_in[8];
    const float* w_chan = (const float*)d_in[9];
    const float* b_chan = (const float*)d_in[10];
    const float* w_proj = (const float*)d_in[11];
    const float* b_proj = (const float*)d_in[12];
    const int*   kptr   = (const int*)d_in[13];
    float* out = (float*)d_out;
    size_t half = (size_t)out_size / 2;

    float *basis45, *cosl, *sinl, *xt, *spec2, *filt, *h, *z1, *z, *t, *tT, *cm, *wprojT;
    float4* coef4; int* coefI;
    cudaGetSymbolAddress((void**)&basis45, g_basis45);
    cudaGetSymbolAddress((void**)&cosl, g_cosl);
    cudaGetSymbolAddress((void**)&sinl, g_sinl);
    cudaGetSymbolAddress((void**)&xt, g_xt);
    cudaGetSymbolAddress((void**)&spec2, g_spec2);
    cudaGetSymbolAddress((void**)&coef4, g_coef4);
    cudaGetSymbolAddress((void**)&coefI, g_coefI);
    cudaGetSymbolAddress((void**)&filt, g_filt);
    cudaGetSymbolAddress((void**)&h, g_h);
    cudaGetSymbolAddress((void**)&z1, g_z1);
    cudaGetSymbolAddress((void**)&z, g_z);
    cudaGetSymbolAddress((void**)&t, g_t);
    cudaGetSymbolAddress((void**)&tT, g_tT);
    cudaGetSymbolAddress((void**)&cm, g_cm);
    cudaGetSymbolAddress((void**)&wprojT, g_wprojT);

    dim3 tb(32, 8);

    // 0) twiddle LUTs + DFT45 half-spectrum basis; w_proj transpose (pad rows stay 0)
    fill_luts<<<(L2F * NB + 255) / 256, 256>>>(basis45, cosl, sinl);
    transpose_ld<<<dim3((PREDL + 31) / 32, H2 / 32, 1), tb>>>(w_proj, wprojT, H2, PREDL, H2);

    // 1) x (b,L,C) -> xt (b,C,L)
    transpose_batched<<<dim3(ENC / 32, (SEQL + 31) / 32, BATCH), tb>>>(x, xt, SEQL, ENC);

    // 2) stage-1 half-spectra (fp32, fused CT permutation)
    gemm_s1<<<NROWS / 8, 256>>>(xt, basis45, spec2);

    // 3) stage-2 combine + top-k -> coef packs
    combine_topk<<<NROWS, 128>>>(spec2, kptr, cosl, sinl, coef4, coefI);

    // 4) fused sparse irfft -> filt AND residual -> first half of d_out
    reconstruct_residual<<<BATCH * (ENC / RCH), 256>>>(
        coef4, coefI, kptr, cosl, sinl, x, filt, out);

    // 5) h = relu(filt @ w_freq + b_freq)   (N=64, K=720)
    gemm_bf<1><<<dim3(1, NROWS / 128), 256>>>(
        filt, SEQL, w_freq, H_FREQ, b_freq, nullptr, 0, h, H_FREQ,
        NROWS, H_FREQ, SEQL, 0, 0, 0, 0);

    // 6) z1 = h @ w_all1[0:64] + b_all1 ; then z1 = relu(xt @ w_all1[64:] + z1)
    gemm_bf<0><<<dim3(H1 / 64, NROWS / 128), 256>>>(
        h, H_FREQ, w_all1, H1, b_all1, nullptr, 0, z1, H1,
        NROWS, H1, H_FREQ, 0, 0, 0, 0);
    gemm_bf<2><<<dim3(H1 / 64, NROWS / 128), 256>>>(
        xt, SEQL, w_all1 + (size_t)H_FREQ * H1, H1, nullptr, z1, H1, z1, H1,
        NROWS, H1, SEQL, 0, 0, 0, 0);

    // 7) z = z1 @ w_all2 + b_all2
    gemm_bf<0><<<dim3(H2 / 64, NROWS / 128), 256>>>(
        z1, H1, w_all2, H2, b_all2, nullptr, 0, z, H2,
        NROWS, H2, H1, 0, 0, 0, 0);

    // 8) t = z + relu(z @ w_time + b_time)
    gemm_bf<3><<<dim3(H2 / 64, NROWS / 128), 256>>>(
        z, H2, w_time, H2, b_time, z, H2, t, H2,
        NROWS, H2, H2, 0, 0, 0, 0);

    // 9) t (b,C,H2) -> tT (b,H2,C)
    transpose_batched<<<dim3(H2 / 32, ENC / 32, BATCH), tb>>>(t, tT, ENC, H2);

    // 10) cm = tT + relu(tT @ w_chan + b_chan)   (rows = b*H2 = 16384, N=K=512)
    gemm_bf<3><<<dim3(ENC / 64, (BATCH * H2) / 128), 256>>>(
        tT, ENC, w_chan, ENC, b_chan, tT, ENC, cm, ENC,
        BATCH * H2, ENC, ENC, 0, 0, 0, 0);

    // 11) out2[b][l][i] = sum_h w_projT[l][h] * cm[b][h][i] + b_proj[l]
    //     batched over b, written DIRECTLY into d_out second half.
    gemm_bf<5><<<dim3(ENC / 64, PREDPAD / 128, BATCH), 256>>>(
        wprojT, H2, cm, ENC, b_proj, nullptr, 0, out + half, ENC,
        PREDL, ENC, H2, 0, (long)H2 * ENC, 0, (long)PREDL * ENC);
}

// round 17
// speedup vs baseline: 1.1027x; 1.0462x over previous
#include <cuda_runtime.h>
#include <cuda_bf16.h>
#include <cstdint>
#include <cstddef>

// ---------------- problem constants ----------------
#define BATCH   64
#define SEQL    720      // L = 16 * 45
#define ENC     512      // C
#define NROWS   (BATCH*ENC)       // 32768
#define NFREQ   361               // rfft bins
#define H_FREQ  64
#define H1      128
#define H2      256
#define PREDL   720
#define PREDPAD 768      // padded M for the output GEMM

#define L1F     16       // first CT factor
#define L2F     45       // second CT factor
#define NB      48       // stage-1 output width: [cos 0..22 | pad | -sin 0..22 | pad]
#define RCH     8        // channels per reconstruct_residual block

// ---------------- scratch (device globals; no allocs allowed) ----------------
__device__ float g_basis45[L2F*NB];           // DFT45 half-spectrum basis
__device__ float g_cosl[SEQL];
__device__ float g_sinl[SEQL];
__device__ float g_xt  [(size_t)NROWS*SEQL];  // x channel-major (b,c,l)
__device__ float g_spec2[(size_t)NROWS*L1F*NB]; // stage-1 partial half-spectra
__device__ float4 g_coef4[(size_t)NROWS*32];  // (re*w, im*w, twid.x, twid.y)
__device__ int    g_coefI[(size_t)NROWS*32];  // selected freq
__device__ float g_filt[(size_t)NROWS*SEQL];
__device__ float g_h   [(size_t)NROWS*H_FREQ];
__device__ float g_z1  [(size_t)NROWS*H1];
__device__ float g_z   [(size_t)NROWS*H2];
__device__ float g_t   [(size_t)NROWS*H2];
__device__ float g_tT  [(size_t)NROWS*H2];    // t transposed per batch (b,h,c)
__device__ float g_cm  [(size_t)NROWS*H2];    // channel-mixed (b,h,c)
__device__ float g_wprojT[(size_t)PREDPAD*H2]; // w_proj^T padded; pad rows stay 0

// ---------------- LUT / basis fill ----------------
__global__ void fill_luts(float* __restrict__ basis45, float* __restrict__ cosl,
                          float* __restrict__ sinl) {
    int idx = blockIdx.x * blockDim.x + threadIdx.x;
    if (idx < SEQL) {
        double s, c;
        sincospi((double)(2 * idx) / (double)SEQL, &s, &c);
        cosl[idx] = (float)c;
        sinl[idx] = (float)s;
    }
    if (idx < L2F * NB) {
        int l2 = idx / NB, c = idx % NB;
        float v = 0.f;
        if (c < 23 || (c >= 24 && c < 47)) {
            int g = (c < 23) ? c : (c - 24);
            int a = (g * l2) % L2F;
            double s, cc;
            sincospi((double)(2 * a) / (double)L2F, &s, &cc);
            v = (c < 23) ? (float)cc : (float)(-s);
        }
        basis45[idx] = v;
    }
}

// ---------------- batched transpose (B,R,C) -> (B,C,R) ----------------
__global__ void transpose_batched(const float* __restrict__ in, float* __restrict__ out,
                                  int R, int C) {
    __shared__ float tile[32][33];
    int b = blockIdx.z;
    int c0 = blockIdx.x * 32, r0 = blockIdx.y * 32;
    const float* pin = in + (size_t)b * R * C;
    float* pout = out + (size_t)b * R * C;
    int tx = threadIdx.x, ty = threadIdx.y;
#pragma unroll
    for (int j = 0; j < 32; j += 8) {
        int r = r0 + ty + j, c = c0 + tx;
        if (r < R && c < C) tile[ty + j][tx] = pin[(size_t)r * C + c];
    }
    __syncthreads();
#pragma unroll
    for (int j = 0; j < 32; j += 8) {
        int c = c0 + ty + j, r = r0 + tx;
        if (c < C && r < R) pout[(size_t)c * R + r] = tile[tx][ty + j];
    }
}

// variant writing into an output with row stride ldo (for padded w_projT)
__global__ void transpose_ld(const float* __restrict__ in, float* __restrict__ out,
                             int R, int C, int ldo) {
    __shared__ float tile[32][33];
    int c0 = blockIdx.x * 32, r0 = blockIdx.y * 32;
    int tx = threadIdx.x, ty = threadIdx.y;
#pragma unroll
    for (int j = 0; j < 32; j += 8) {
        int r = r0 + ty + j, c = c0 + tx;
        if (r < R && c < C) tile[ty + j][tx] = in[(size_t)r * C + c];
    }
    __syncthreads();
#pragma unroll
    for (int j = 0; j < 32; j += 8) {
        int c = c0 + ty + j, r = r0 + tx;
        if (c < C && r < R) out[(size_t)c * ldo + r] = tile[tx][ty + j];
    }
}

// ------- stage-1: per-block 8 xt rows x full DFT45 half-spectrum (fp32) -------
__global__ void __launch_bounds__(256) gemm_s1(
    const float* __restrict__ xt, const float* __restrict__ basis,
    float* __restrict__ spec2) {
    __shared__ float Axt[8][SEQL];
    __shared__ float Bs[L2F][NB];
    const int tid = threadIdx.x;
    const size_t base = (size_t)blockIdx.x * (8 * SEQL);

    {
        const float4* src = reinterpret_cast<const float4*>(xt + base);
        float4* dst = reinterpret_cast<float4*>(&Axt[0][0]);
        for (int i = tid; i < 8 * SEQL / 4; i += 256) dst[i] = src[i];
    }
    {
        const float4* src = reinterpret_cast<const float4*>(basis);
        float4* dst = reinterpret_cast<float4*>(&Bs[0][0]);
        for (int i = tid; i < L2F * NB / 4; i += 256) dst[i] = src[i];
    }
    __syncthreads();

    const int tm = (tid >> 3) * 4;
    const int tn = (tid & 7) * 6;
    const int orig = tm >> 4;
    const int l1b = tm & 15;

    float acc[4][6] = {};
#pragma unroll 15
    for (int k = 0; k < L2F; k++) {
        float4 av = *reinterpret_cast<const float4*>(&Axt[orig][l1b + 16 * k]);
        float2 b0 = *reinterpret_cast<const float2*>(&Bs[k][tn]);
        float2 b1 = *reinterpret_cast<const float2*>(&Bs[k][tn + 2]);
        float2 b2 = *reinterpret_cast<const float2*>(&Bs[k][tn + 4]);
        float a[4] = {av.x, av.y, av.z, av.w};
        float b[6] = {b0.x, b0.y, b1.x, b1.y, b2.x, b2.y};
#pragma unroll
        for (int i = 0; i < 4; i++)
#pragma unroll
            for (int j = 0; j < 6; j++)
                acc[i][j] = fmaf(a[i], b[j], acc[i][j]);
    }

    size_t gmbase = (size_t)blockIdx.x * 128 + tm;
#pragma unroll
    for (int i = 0; i < 4; i++) {
        float* orow = spec2 + (gmbase + i) * NB + tn;
#pragma unroll
        for (int j = 0; j < 6; j += 2)
            *reinterpret_cast<float2*>(&orow[j]) = make_float2(acc[i][j], acc[i][j + 1]);
    }
}

// ------- stage-2 twiddle combine + per-row top-k selection -> coef packs -------
__global__ void __launch_bounds__(128) combine_topk(
    const float* __restrict__ spec2, const int* __restrict__ kptr,
    const float* __restrict__ cosl, const float* __restrict__ sinl,
    float4* __restrict__ coef4, int* __restrict__ coefI) {
    int row = blockIdx.x;
    const float* srow = spec2 + (size_t)row * (L1F * NB);

    __shared__ float2 slut[SEQL];
    __shared__ float2 sS2[L1F][23];
    __shared__ float sXre[NFREQ], sXim[NFREQ], sMag[NFREQ];

    int tid = threadIdx.x;
    for (int i = tid; i < SEQL; i += 128) slut[i] = make_float2(cosl[i], sinl[i]);
    for (int i = tid; i < L1F * 23; i += 128) {
        int l1 = i / 23, g = i % 23;
        sS2[l1][g] = make_float2(srow[l1 * NB + g], srow[l1 * NB + 24 + g]);
    }
    __syncthreads();

    for (int f = tid; f < NFREQ; f += 128) {
        int g = f % L2F;
        int gc = g; float sgn = 1.f;
        if (g >= 23) { gc = L2F - g; sgn = -1.f; }
        float xr = 0.f, xi = 0.f;
        int a = 0;
#pragma unroll
        for (int l1 = 0; l1 < L1F; l1++) {
            float2 w = slut[a];
            float2 s = sS2[l1][gc];
            float sr = s.x;
            float si = sgn * s.y;
            xr = fmaf(sr, w.x, fmaf(si, w.y, xr));
            xi = fmaf(si, w.x, fmaf(-sr, w.y, xi));
            a += f; if (a >= SEQL) a -= SEQL;
        }
        sXre[f] = xr; sXim[f] = xi;
        sMag[f] = xr * xr + xi * xi;
    }
    __syncthreads();

    if (tid < 32) {
        int lane = tid;
        float mag[12];
#pragma unroll
        for (int j = 0; j < 12; j++) {
            int idx = lane + 32 * j;
            mag[j] = (idx < NFREQ) ? sMag[idx] : -1.f;
        }
        int k = *kptr;
        if (k > 32) k = 32;
        if (k < 0) k = 0;
        const float scale = 1.f / (float)SEQL;
        for (int it = 0; it < k; it++) {
            float best = -1.f; int bslot = 0;
#pragma unroll
            for (int j = 0; j < 12; j++)
                if (mag[j] > best) { best = mag[j]; bslot = j; }
            int bidx = lane + 32 * bslot;
#pragma unroll
            for (int o = 16; o > 0; o >>= 1) {
                float ov = __shfl_xor_sync(0xffffffffu, best, o);
                int   oi = __shfl_xor_sync(0xffffffffu, bidx, o);
                if (ov > best || (ov == best && oi < bidx)) { best = ov; bidx = oi; }
            }
            if ((bidx & 31) == lane) {
                int j = bidx >> 5;
                float w = (bidx == 0 || bidx == NFREQ - 1) ? scale : 2.f * scale;
                float2 tw = slut[bidx];
                coef4[(size_t)row * 32 + it] =
                    make_float4(sXre[bidx] * w, sXim[bidx] * w, tw.x, tw.y);
                coefI[(size_t)row * 32 + it] = bidx;
                mag[j] = -2.f;
            }
        }
    }
}

// ------- fused: sparse rotation irfft + filt write + residual (x - filt^T) -------
__global__ void __launch_bounds__(256) reconstruct_residual(
    const float4* __restrict__ coef4, const int* __restrict__ coefI,
    const int* __restrict__ kptr,
    const float* __restrict__ cosl, const float* __restrict__ sinl,
    const float* __restrict__ x,
    float* __restrict__ filt, float* __restrict__ outres) {
    __shared__ float2 slut[SEQL];
    __shared__ float4 sc[RCH][32];
    __shared__ int    sf[RCH][32];
    __shared__ float  sfilt[RCH][SEQL + 1];   // 721 stride: spreads banks

    int tid = threadIdx.x;
    int b = blockIdx.x >> 6;                  // ENC/RCH = 64 blocks per batch
    int cblk = blockIdx.x & 63;
    size_t row0 = (size_t)b * ENC + (size_t)cblk * RCH;

    for (int i = tid; i < SEQL; i += 256) slut[i] = make_float2(cosl[i], sinl[i]);
    int k = *kptr;
    if (k > 32) k = 32;
    if (k < 0) k = 0;
    for (int i = tid; i < RCH * 32; i += 256) {
        int ch = i >> 5, j = i & 31;
        if (j < k) {
            sc[ch][j] = coef4[(row0 + ch) * 32 + j];
            sf[ch][j] = coefI[(row0 + ch) * 32 + j];
        }
    }
    __syncthreads();

    if (tid < 240) {
        int t0 = 3 * tid;
#pragma unroll
        for (int ch = 0; ch < RCH; ch++) {
            float acc0 = 0.f, acc1 = 0.f, acc2 = 0.f;
            for (int j = 0; j < k; j++) {
                float4 c4 = sc[ch][j];
                int f = sf[ch][j];
                float r = c4.x, m = c4.y;
                int a0 = (f * t0) % SEQL;
                float2 p0 = slut[a0];
                acc0 = fmaf(r, p0.x, fmaf(-m, p0.y, acc0));
                float2 p1;
                p1.x = fmaf(-p0.y, c4.w, p0.x * c4.z);
                p1.y = fmaf(p0.x, c4.w, p0.y * c4.z);
                acc1 = fmaf(r, p1.x, fmaf(-m, p1.y, acc1));
                float2 p2;
                p2.x = fmaf(-p1.y, c4.w, p1.x * c4.z);
                p2.y = fmaf(p1.x, c4.w, p1.y * c4.z);
                acc2 = fmaf(r, p2.x, fmaf(-m, p2.y, acc2));
            }
            sfilt[ch][t0 + 0] = acc0;
            sfilt[ch][t0 + 1] = acc1;
            sfilt[ch][t0 + 2] = acc2;
        }
    }
    __syncthreads();

    // write filt (b,c,l) coalesced -- consumed by the MLPfreq GEMM
    float* fp = filt + row0 * SEQL;
#pragma unroll
    for (int ch = 0; ch < RCH; ch++)
        for (int l = tid; l < SEQL; l += 256)
            fp[(size_t)ch * SEQL + l] = sfilt[ch][l];

    // residual out[b][l][c0+j] = x[b][l][c0+j] - filt[c0+j][l]
    const float* xb = x + (size_t)b * SEQL * ENC + (size_t)cblk * RCH;
    float* ob = outres + (size_t)b * SEQL * ENC + (size_t)cblk * RCH;
    for (int i = tid; i < SEQL * RCH; i += 256) {
        int l = i >> 3, j = i & 7;
        ob[(size_t)l * ENC + j] = xb[(size_t)l * ENC + j] - sfilt[j][l];
    }
}

// ---------------- bf16 helpers ----------------
__device__ __forceinline__ void split_pack_bf16(float e, float o, uint32_t& hi, uint32_t& lo) {
    __nv_bfloat16 he = __float2bfloat16_rn(e);
    __nv_bfloat16 ho = __float2bfloat16_rn(o);
    float re = e - __bfloat162float(he);
    float ro = o - __bfloat162float(ho);
    __nv_bfloat16 le = __float2bfloat16_rn(re);
    __nv_bfloat16 lo2 = __float2bfloat16_rn(ro);
    unsigned short ue = *reinterpret_cast<unsigned short*>(&he);
    unsigned short uo = *reinterpret_cast<unsigned short*>(&ho);
    unsigned short ve = *reinterpret_cast<unsigned short*>(&le);
    unsigned short vo = *reinterpret_cast<unsigned short*>(&lo2);
    hi = ((uint32_t)uo << 16) | ue;
    lo = ((uint32_t)vo << 16) | ve;
}

__device__ __forceinline__ void mma_bf16(float* d, const uint32_t* a, const uint32_t* b) {
    asm volatile(
        "mma.sync.aligned.m16n8k16.row.col.f32.bf16.bf16.f32 "
        "{%0,%1,%2,%3}, {%4,%5,%6,%7}, {%8,%9}, {%0,%1,%2,%3};\n"
        : "+f"(d[0]), "+f"(d[1]), "+f"(d[2]), "+f"(d[3])
        : "r"(a[0]), "r"(a[1]), "r"(a[2]), "r"(a[3]), "r"(b[0]), "r"(b[1]));
}

// ------- tensor-core GEMM: 128M x NT-N block, bf16 3-term split, m16n8k16 -------
// NT = 64: warp tile 32x32 (proven round-12 config). NT = 128: warp tile 32x64
// (B frags loaded per-ni to cap live registers; per-element accumulation order
// identical to NT=64, so results are bitwise unchanged).
// MODE 0: +bias[col] ; 1: relu ; 2: relu(+Cin) ; 3: Cin + relu ; 5: +bias[row]
template <int MODE, int NT>
__global__ void __launch_bounds__(256) gemm_bf(
    const float* __restrict__ A, int lda,
    const float* __restrict__ B, int ldb,
    const float* __restrict__ bias,
    const float* __restrict__ Cin, int ldcin,
    float* __restrict__ C, int ldc,
    int M, int N, int K,
    long zA, long zB, long zCin, long zC) {
    constexpr int NI = NT / 16;          // ni-tiles per warp (4 or 8)
    constexpr int BPAD = NT + 12;        // 76 / 140: bank-spread rows
    constexpr int BN = NT / 32;          // B n-values per loader thread (2 or 4)
    __shared__ uint2 As[8][140];         // [kp][m] (hi, lo)
    __shared__ uint2 Bs[8][BPAD];        // [kp][n]

    const size_t zi = blockIdx.z;
    A += zi * zA; B += zi * zB;
    if (Cin) Cin += zi * zCin;
    C += zi * zC;

    const int tid = threadIdx.x;
    const int m0 = blockIdx.y * 128, n0 = blockIdx.x * NT;
    const int lane = tid & 31, warp = tid >> 5;
    const int wm = warp & 3, wn = warp >> 2;
    const int m0w = wm * 32, n0w = wn * (NT / 2);
    const int kq = lane & 3, gq = lane >> 2;

    const int arow = tid >> 1, ak = (tid & 1) * 8, akp = (tid & 1) * 4;
    const int bkp = tid >> 5, bnb = (tid & 31) * BN;

    float acc[2][NI][4];
#pragma unroll
    for (int i = 0; i < 2; i++)
#pragma unroll
        for (int j = 0; j < NI; j++)
#pragma unroll
            for (int q = 0; q < 4; q++) acc[i][j][q] = 0.f;

    // prefetch first tile
    float4 aP0 = *reinterpret_cast<const float4*>(&A[(size_t)(m0 + arow) * lda + ak]);
    float4 aP1 = *reinterpret_cast<const float4*>(&A[(size_t)(m0 + arow) * lda + ak + 4]);
    float be[BN], bo[BN];
    {
        const float* B0 = &B[(size_t)(2 * bkp) * ldb];
        const float* B1 = &B[(size_t)(2 * bkp + 1) * ldb];
#pragma unroll
        for (int i = 0; i < BN; i++) {
            int n = n0 + bnb + i;
            be[i] = (n < N) ? B0[n] : 0.f;
            bo[i] = (n < N) ? B1[n] : 0.f;
        }
    }

    for (int k0 = 0; k0 < K; k0 += 16) {
        {
            float av[8] = {aP0.x, aP0.y, aP0.z, aP0.w, aP1.x, aP1.y, aP1.z, aP1.w};
#pragma unroll
            for (int i = 0; i < 4; i++) {
                uint32_t h, l;
                split_pack_bf16(av[2 * i], av[2 * i + 1], h, l);
                As[akp + i][arow] = make_uint2(h, l);
            }
#pragma unroll
            for (int i = 0; i < BN; i++) {
                uint32_t h, l;
                split_pack_bf16(be[i], bo[i], h, l);
                Bs[bkp][bnb + i] = make_uint2(h, l);
            }
        }
        __syncthreads();

        if (k0 + 16 < K) {
            aP0 = *reinterpret_cast<const float4*>(&A[(size_t)(m0 + arow) * lda + (k0 + 16 + ak)]);
            aP1 = *reinterpret_cast<const float4*>(&A[(size_t)(m0 + arow) * lda + (k0 + 16 + ak + 4)]);
            const float* B0 = &B[(size_t)(k0 + 16 + 2 * bkp) * ldb];
            const float* B1 = &B[(size_t)(k0 + 16 + 2 * bkp + 1) * ldb];
#pragma unroll
            for (int i = 0; i < BN; i++) {
                int n = n0 + bnb + i;
                be[i] = (n < N) ? B0[n] : 0.f;
                bo[i] = (n < N) ? B1[n] : 0.f;
            }
        }

        // one k16 MMA sweep
        uint32_t ah[2][4], al[2][4];
#pragma unroll
        for (int mi = 0; mi < 2; mi++) {
            int m = m0w + mi * 16 + gq;
            uint2 a00 = As[kq][m],     a01 = As[kq][m + 8];
            uint2 a10 = As[kq + 4][m], a11 = As[kq + 4][m + 8];
            ah[mi][0] = a00.x; ah[mi][1] = a01.x; ah[mi][2] = a10.x; ah[mi][3] = a11.x;
            al[mi][0] = a00.y; al[mi][1] = a01.y; al[mi][2] = a10.y; al[mi][3] = a11.y;
        }
#pragma unroll
        for (int ni = 0; ni < NI; ni++) {
            int n = n0w + ni * 8 + gq;
            uint2 b0 = Bs[kq][n], b1 = Bs[kq + 4][n];
            uint32_t bh[2] = {b0.x, b1.x};
            uint32_t bl[2] = {b0.y, b1.y};
#pragma unroll
            for (int mi = 0; mi < 2; mi++) {
                mma_bf16(acc[mi][ni], ah[mi], bh);
                mma_bf16(acc[mi][ni], al[mi], bh);
                mma_bf16(acc[mi][ni], ah[mi], bl);
            }
        }
        __syncthreads();
    }

    // epilogue
#pragma unroll
    for (int mi = 0; mi < 2; mi++)
#pragma unroll
        for (int ni = 0; ni < NI; ni++)
#pragma unroll
            for (int hf = 0; hf < 2; hf++) {
                int gm = m0 + m0w + mi * 16 + gq + hf * 8;
                if (gm >= M) continue;
                int gn = n0 + n0w + ni * 8 + kq * 2;
                float v0 = acc[mi][ni][hf * 2 + 0];
                float v1 = acc[mi][ni][hf * 2 + 1];
                bool ok0 = (gn < N), ok1 = (gn + 1 < N);
                if (MODE != 5 && bias) {
                    if (ok0) v0 += bias[gn];
                    if (ok1) v1 += bias[gn + 1];
                }
                if (MODE == 1) { v0 = fmaxf(v0, 0.f); v1 = fmaxf(v1, 0.f); }
                else if (MODE == 2) {
                    if (ok0) v0 += Cin[(size_t)gm * ldcin + gn];
                    if (ok1) v1 += Cin[(size_t)gm * ldcin + gn + 1];
                    v0 = fmaxf(v0, 0.f); v1 = fmaxf(v1, 0.f);
                } else if (MODE == 3) {
                    if (ok0) v0 = Cin[(size_t)gm * ldcin + gn] + fmaxf(v0, 0.f);
                    if (ok1) v1 = Cin[(size_t)gm * ldcin + gn + 1] + fmaxf(v1, 0.f);
                } else if (MODE == 5) {
                    float bb = bias[gm];
                    v0 += bb; v1 += bb;
                }
                if (ok0) C[(size_t)gm * ldc + gn]     = v0;
                if (ok1) C[(size_t)gm * ldc + gn + 1] = v1;
            }
}

// ---------------- host launch ----------------
extern "C" void kernel_launch(void* const* d_in, const int* in_sizes, int n_in,
                              void* d_out, int out_size) {
    const float* x      = (const float*)d_in[0];
    const float* w_freq = (const float*)d_in[1];
    const float* b_freq = (const float*)d_in[2];
    const float* w_all1 = (const float*)d_in[3];
    const float* b_all1 = (const float*)d_in[4];
    const float* w_all2 = (const float*)d_in[5];
    const float* b_all2 = (const float*)d_in[6];
    const float* w_time = (const float*)d_in[7];
    const float* b_time = (const float*)d_in[8];
    const float* w_chan = (const float*)d_in[9];
    const float* b_chan = (const float*)d_in[10];
    const float* w_proj = (const float*)d_in[11];
    const float* b_proj = (const float*)d_in[12];
    const int*   kptr   = (const int*)d_in[13];
    float* out = (float*)d_out;
    size_t half = (size_t)out_size / 2;

    float *basis45, *cosl, *sinl, *xt, *spec2, *filt, *h, *z1, *z, *t, *tT, *cm, *wprojT;
    float4* coef4; int* coefI;
    cudaGetSymbolAddress((void**)&basis45, g_basis45);
    cudaGetSymbolAddress((void**)&cosl, g_cosl);
    cudaGetSymbolAddress((void**)&sinl, g_sinl);
    cudaGetSymbolAddress((void**)&xt, g_xt);
    cudaGetSymbolAddress((void**)&spec2, g_spec2);
    cudaGetSymbolAddress((void**)&coef4, g_coef4);
    cudaGetSymbolAddress((void**)&coefI, g_coefI);
    cudaGetSymbolAddress((void**)&filt, g_filt);
    cudaGetSymbolAddress((void**)&h, g_h);
    cudaGetSymbolAddress((void**)&z1, g_z1);
    cudaGetSymbolAddress((void**)&z, g_z);
    cudaGetSymbolAddress((void**)&t, g_t);
    cudaGetSymbolAddress((void**)&tT, g_tT);
    cudaGetSymbolAddress((void**)&cm, g_cm);
    cudaGetSymbolAddress((void**)&wprojT, g_wprojT);

    dim3 tb(32, 8);

    // 0) twiddle LUTs + DFT45 half-spectrum basis; w_proj transpose (pad rows stay 0)
    fill_luts<<<(L2F * NB + 255) / 256, 256>>>(basis45, cosl, sinl);
    transpose_ld<<<dim3((PREDL + 31) / 32, H2 / 32, 1), tb>>>(w_proj, wprojT, H2, PREDL, H2);

    // 1) x (b,L,C) -> xt (b,C,L)
    transpose_batched<<<dim3(ENC / 32, (SEQL + 31) / 32, BATCH), tb>>>(x, xt, SEQL, ENC);

    // 2) stage-1 half-spectra (fp32, fused CT permutation)
    gemm_s1<<<NROWS / 8, 256>>>(xt, basis45, spec2);

    // 3) stage-2 combine + top-k -> coef packs
    combine_topk<<<NROWS, 128>>>(spec2, kptr, cosl, sinl, coef4, coefI);

    // 4) fused sparse irfft -> filt AND residual -> first half of d_out
    reconstruct_residual<<<BATCH * (ENC / RCH), 256>>>(
        coef4, coefI, kptr, cosl, sinl, x, filt, out);

    // 5) h = relu(filt @ w_freq + b_freq)   (N=64, K=720) -- NT=64
    gemm_bf<1, 64><<<dim3(1, NROWS / 128), 256>>>(
        filt, SEQL, w_freq, H_FREQ, b_freq, nullptr, 0, h, H_FREQ,
        NROWS, H_FREQ, SEQL, 0, 0, 0, 0);

    // 6) z1 = h @ w_all1[0:64] + b_all1 ; then z1 = relu(xt @ w_all1[64:] + z1)
    gemm_bf<0, 128><<<dim3(1, NROWS / 128), 256>>>(
        h, H_FREQ, w_all1, H1, b_all1, nullptr, 0, z1, H1,
        NROWS, H1, H_FREQ, 0, 0, 0, 0);
    gemm_bf<2, 128><<<dim3(1, NROWS / 128), 256>>>(
        xt, SEQL, w_all1 + (size_t)H_FREQ * H1, H1, nullptr, z1, H1, z1, H1,
        NROWS, H1, SEQL, 0, 0, 0, 0);

    // 7) z = z1 @ w_all2 + b_all2
    gemm_bf<0, 128><<<dim3(H2 / 128, NROWS / 128), 256>>>(
        z1, H1, w_all2, H2, b_all2, nullptr, 0, z, H2,
        NROWS, H2, H1, 0, 0, 0, 0);

    // 8) t = z + relu(z @ w_time + b_time)
    gemm_bf<3, 128><<<dim3(H2 / 128, NROWS / 128), 256>>>(
        z, H2, w_time, H2, b_time, z, H2, t, H2,
        NROWS, H2, H2, 0, 0, 0, 0);

    // 9) t (b,C,H2) -> tT (b,H2,C)
    transpose_batched<<<dim3(H2 / 32, ENC / 32, BATCH), tb>>>(t, tT, ENC, H2);

    // 10) cm = tT + relu(tT @ w_chan + b_chan)   (rows = b*H2 = 16384, N=K=512)
    gemm_bf<3, 128><<<dim3(ENC / 128, (BATCH * H2) / 128), 256>>>(
        tT, ENC, w_chan, ENC, b_chan, tT, ENC, cm, ENC,
        BATCH * H2, ENC, ENC, 0, 0, 0, 0);

    // 11) out2[b][l][i] = sum_h w_projT[l][h] * cm[b][h][i] + b_proj[l]
    //     batched over b, written DIRECTLY into d_out second half.
    gemm_bf<5, 128><<<dim3(ENC / 128, PREDPAD / 128, BATCH), 256>>>(
        wprojT, H2, cm, ENC, b_proj, nullptr, 0, out + half, ENC,
        PREDL, ENC, H2, 0, (long)H2 * ENC, 0, (long)PREDL * ENC);
}